// round 1
// baseline (speedup 1.0000x reference)
#include <cuda_runtime.h>
#include <cuda_bf16.h>
#include <cstdint>
#include <cstdio>

// Problem constants
#define LNUM 18
#define BB 8
#define CC 50
#define AA 32
#define HH 1024
#define NHH 8
#define NKV 1
#define HD 256
#define PP 800
#define MLPD 4096
#define MTOT (BB*CC)          // 400
#define TTOT (PP+CC)          // 850

// ---------------- scratch (device globals; no allocation allowed) ----------------
__device__ float g_x[MTOT*HH];
__device__ float g_h[MTOT*HH];
__device__ float g_xt[MTOT*2*HH];
__device__ float g_q[MTOT*NHH*HD];
__device__ float g_k[MTOT*HD];
__device__ float g_v[MTOT*HD];
__device__ float g_ao[MTOT*NHH*HD];
__device__ float g_s[BB*NHH*CC*TTOT];    // 2.72M floats
__device__ float g_gate[MTOT*MLPD];
__device__ float g_up[MTOT*MLPD];

// ---------------- block reduction helper ----------------
__device__ __forceinline__ float blk_reduce(float v, bool ismax) {
    __shared__ float sh[8];
    int lane = threadIdx.x & 31, wid = threadIdx.x >> 5;
    #pragma unroll
    for (int o = 16; o > 0; o >>= 1) {
        float w = __shfl_xor_sync(0xffffffffu, v, o);
        v = ismax ? fmaxf(v, w) : (v + w);
    }
    if (lane == 0) sh[wid] = v;
    __syncthreads();
    if (threadIdx.x == 0) {
        float r = sh[0];
        #pragma unroll
        for (int i = 1; i < 8; i++) r = ismax ? fmaxf(r, sh[i]) : (r + sh[i]);
        sh[0] = r;
    }
    __syncthreads();
    float r = sh[0];
    __syncthreads();
    return r;
}

// ---------------- generic NT GEMM: C[M,N] = A[M,K] @ B[N,K]^T (+epilogue) ----------------
// EPI bit0: +bias[n], bit1: += C_old (residual accumulate), bit2: silu
#define GBM 128
#define GBN 64
#define GBK 16

template<int EPI>
__global__ void __launch_bounds__(256) gemm_nt(
    const float* __restrict__ A, const float* __restrict__ B,
    const float* __restrict__ bias, float* __restrict__ C,
    int M, int N, int K, int lda, int ldb, int ldc)
{
    __shared__ float As[GBK][GBM + 4];
    __shared__ float Bs[GBK][GBN + 4];
    int m0 = blockIdx.y * GBM, n0 = blockIdx.x * GBN;
    int tid = threadIdx.x;
    int ty = tid >> 4, tx = tid & 15;   // 16x16 thread grid

    float acc[8][4];
    #pragma unroll
    for (int i = 0; i < 8; i++)
        #pragma unroll
        for (int j = 0; j < 4; j++) acc[i][j] = 0.f;

    for (int k0 = 0; k0 < K; k0 += GBK) {
        #pragma unroll
        for (int e = 0; e < 8; e++) {
            int idx = tid + e * 256;
            int r = idx >> 4, c = idx & 15;
            int gm = m0 + r, gk = k0 + c;
            As[c][r] = (gm < M && gk < K) ? A[(size_t)gm * lda + gk] : 0.f;
        }
        #pragma unroll
        for (int e = 0; e < 4; e++) {
            int idx = tid + e * 256;
            int r = idx >> 4, c = idx & 15;
            int gn = n0 + r, gk = k0 + c;
            Bs[c][r] = (gn < N && gk < K) ? B[(size_t)gn * ldb + gk] : 0.f;
        }
        __syncthreads();
        #pragma unroll
        for (int kk = 0; kk < GBK; kk++) {
            float a[8], bv[4];
            #pragma unroll
            for (int i = 0; i < 8; i++) a[i] = As[kk][ty * 8 + i];
            #pragma unroll
            for (int j = 0; j < 4; j++) bv[j] = Bs[kk][tx * 4 + j];
            #pragma unroll
            for (int i = 0; i < 8; i++)
                #pragma unroll
                for (int j = 0; j < 4; j++)
                    acc[i][j] = fmaf(a[i], bv[j], acc[i][j]);
        }
        __syncthreads();
    }

    #pragma unroll
    for (int i = 0; i < 8; i++) {
        int gm = m0 + ty * 8 + i;
        if (gm >= M) continue;
        #pragma unroll
        for (int j = 0; j < 4; j++) {
            int gn = n0 + tx * 4 + j;
            if (gn >= N) continue;
            float v = acc[i][j];
            if (EPI & 1) v += bias[gn];
            if (EPI & 2) v += C[(size_t)gm * ldc + gn];
            if (EPI & 4) v = v / (1.f + expf(-v));   // silu
            C[(size_t)gm * ldc + gn] = v;
        }
    }
}

static void launch_gemm(const float* A, const float* B, const float* bias, float* C,
                        int M, int N, int K, int lda, int ldb, int ldc, int epi)
{
    dim3 grid((N + GBN - 1) / GBN, (M + GBM - 1) / GBM);
    switch (epi) {
        case 0: gemm_nt<0><<<grid, 256>>>(A, B, bias, C, M, N, K, lda, ldb, ldc); break;
        case 1: gemm_nt<1><<<grid, 256>>>(A, B, bias, C, M, N, K, lda, ldb, ldc); break;
        case 2: gemm_nt<2><<<grid, 256>>>(A, B, bias, C, M, N, K, lda, ldb, ldc); break;
        case 5: gemm_nt<5><<<grid, 256>>>(A, B, bias, C, M, N, K, lda, ldb, ldc); break;
    }
}

// ---------------- attention scores: S[b,n,c,t] = scale * q[b,c,n,:] . K_cat[b,t,:] ----------------
__global__ void __launch_bounds__(256) attn_scores_kernel(
    const float* __restrict__ q, const float* __restrict__ pk,
    const float* __restrict__ knew, float* __restrict__ S, int layer)
{
    __shared__ float As[16][68], Bs[16][68];
    int z = blockIdx.z; int b = z >> 3, n = z & 7;
    int t0 = blockIdx.x * 64;
    int tid = threadIdx.x, ty = tid >> 4, tx = tid & 15;
    const float* qb  = q + (size_t)(b * CC) * (NHH * HD) + n * HD;
    const float* pkb = pk + ((size_t)layer * BB + b) * PP * HD;
    const float* kb  = knew + (size_t)(b * CC) * HD;

    float acc[4][4];
    #pragma unroll
    for (int i = 0; i < 4; i++)
        #pragma unroll
        for (int j = 0; j < 4; j++) acc[i][j] = 0.f;

    for (int k0 = 0; k0 < HD; k0 += 16) {
        #pragma unroll
        for (int e = 0; e < 4; e++) {
            int idx = tid + e * 256;
            int r = idx >> 4, c = idx & 15;
            As[c][r] = (r < CC) ? qb[(size_t)r * (NHH * HD) + k0 + c] : 0.f;
            int t = t0 + r; float vv = 0.f;
            if (t < PP) vv = pkb[(size_t)t * HD + k0 + c];
            else if (t < TTOT) vv = kb[(size_t)(t - PP) * HD + k0 + c];
            Bs[c][r] = vv;
        }
        __syncthreads();
        #pragma unroll
        for (int kk = 0; kk < 16; kk++) {
            float a[4], bv[4];
            #pragma unroll
            for (int i = 0; i < 4; i++) a[i] = As[kk][ty * 4 + i];
            #pragma unroll
            for (int j = 0; j < 4; j++) bv[j] = Bs[kk][tx * 4 + j];
            #pragma unroll
            for (int i = 0; i < 4; i++)
                #pragma unroll
                for (int j = 0; j < 4; j++)
                    acc[i][j] = fmaf(a[i], bv[j], acc[i][j]);
        }
        __syncthreads();
    }

    float* Sb = S + (size_t)z * CC * TTOT;
    const float scale = 0.0625f;   // 1/sqrt(256)
    #pragma unroll
    for (int i = 0; i < 4; i++) {
        int c = ty * 4 + i;
        if (c >= CC) continue;
        #pragma unroll
        for (int j = 0; j < 4; j++) {
            int t = t0 + tx * 4 + j;
            if (t < TTOT) Sb[(size_t)c * TTOT + t] = acc[i][j] * scale;
        }
    }
}

// ---------------- softmax over t (in place), rows = B*NH*C = 3200 ----------------
__global__ void __launch_bounds__(256) softmax_kernel(float* __restrict__ S)
{
    int row = blockIdx.x;
    float* s = S + (size_t)row * TTOT;
    float vals[4];
    float mx = -1e30f;
    #pragma unroll
    for (int ii = 0; ii < 4; ii++) {
        int j = threadIdx.x + ii * 256;
        vals[ii] = (j < TTOT) ? s[j] : -1e30f;
        mx = fmaxf(mx, vals[ii]);
    }
    mx = blk_reduce(mx, true);
    float sum = 0.f;
    #pragma unroll
    for (int ii = 0; ii < 4; ii++) {
        int j = threadIdx.x + ii * 256;
        if (j < TTOT) { vals[ii] = expf(vals[ii] - mx); sum += vals[ii]; }
    }
    sum = blk_reduce(sum, false);
    float inv = 1.f / sum;
    #pragma unroll
    for (int ii = 0; ii < 4; ii++) {
        int j = threadIdx.x + ii * 256;
        if (j < TTOT) s[j] = vals[ii] * inv;
    }
}

// ---------------- AV: O[b,c,n,d] = sum_t P[b,n,c,t] * V_cat[b,t,d] ----------------
__global__ void __launch_bounds__(256) attn_av_kernel(
    const float* __restrict__ S, const float* __restrict__ pv,
    const float* __restrict__ vnew, float* __restrict__ O, int layer)
{
    __shared__ float As[16][68];   // As[kk][c]
    __shared__ float Bs[16][68];   // Bs[kk][d]
    int z = blockIdx.z; int b = z >> 3, n = z & 7;
    int d0 = blockIdx.x * 64;
    int tid = threadIdx.x, ty = tid >> 4, tx = tid & 15;
    const float* Sb  = S + (size_t)z * CC * TTOT;
    const float* pvb = pv + ((size_t)layer * BB + b) * PP * HD;
    const float* vb  = vnew + (size_t)(b * CC) * HD;

    float acc[4][4];
    #pragma unroll
    for (int i = 0; i < 4; i++)
        #pragma unroll
        for (int j = 0; j < 4; j++) acc[i][j] = 0.f;

    for (int k0 = 0; k0 < TTOT; k0 += 16) {
        #pragma unroll
        for (int e = 0; e < 4; e++) {
            int idx = tid + e * 256;
            int r = idx >> 4, c = idx & 15;
            int gk = k0 + c;
            As[c][r] = (r < CC && gk < TTOT) ? Sb[(size_t)r * TTOT + gk] : 0.f;
        }
        #pragma unroll
        for (int e = 0; e < 4; e++) {
            int idx = tid + e * 256;
            int r = idx >> 6, c = idx & 63;
            int t = k0 + r; float vv = 0.f;
            if (t < PP) vv = pvb[(size_t)t * HD + d0 + c];
            else if (t < TTOT) vv = vb[(size_t)(t - PP) * HD + d0 + c];
            Bs[r][c] = vv;
        }
        __syncthreads();
        #pragma unroll
        for (int kk = 0; kk < 16; kk++) {
            float a[4], bv[4];
            #pragma unroll
            for (int i = 0; i < 4; i++) a[i] = As[kk][ty * 4 + i];
            #pragma unroll
            for (int j = 0; j < 4; j++) bv[j] = Bs[kk][tx * 4 + j];
            #pragma unroll
            for (int i = 0; i < 4; i++)
                #pragma unroll
                for (int j = 0; j < 4; j++)
                    acc[i][j] = fmaf(a[i], bv[j], acc[i][j]);
        }
        __syncthreads();
    }

    #pragma unroll
    for (int i = 0; i < 4; i++) {
        int c = ty * 4 + i;
        if (c >= CC) continue;
        #pragma unroll
        for (int j = 0; j < 4; j++) {
            int d = d0 + tx * 4 + j;
            O[(size_t)(b * CC + c) * (NHH * HD) + n * HD + d] = acc[i][j];
        }
    }
}

// ---------------- rmsnorm: out[row,:] = x[row,:] * rsqrt(mean(x^2)+eps) * w ----------------
__global__ void __launch_bounds__(256) rmsnorm_kernel(
    const float* __restrict__ x, const float* __restrict__ w, float* __restrict__ out)
{
    int row = blockIdx.x;
    const float* xr = x + (size_t)row * HH;
    float ss = 0.f;
    for (int j = threadIdx.x; j < HH; j += 256) { float v = xr[j]; ss += v * v; }
    ss = blk_reduce(ss, false);
    float sc = rsqrtf(ss * (1.f / HH) + 1e-6f);
    for (int j = threadIdx.x; j < HH; j += 256)
        out[(size_t)row * HH + j] = xr[j] * sc * w[j];
}

// ---------------- rope (in place), half-pair update ----------------
__global__ void rope_kernel(float* __restrict__ x, const int* __restrict__ pos_ids, int nh)
{
    int idx = blockIdx.x * blockDim.x + threadIdx.x;
    int total = MTOT * nh * (HD / 2);
    if (idx >= total) return;
    int i = idx & 127;            // 0..127
    int mn = idx >> 7;            // m*nh + n
    int m = mn / nh;
    int c = m % CC;
    float pos = (float)pos_ids[c];
    // inv = 10000^(-i/128)
    float inv = expf(-(float)i * (9.210340371976184f / 128.f));
    float ang = pos * inv;
    float cs = cosf(ang), sn = sinf(ang);
    float* p = x + (size_t)mn * HD;
    float x1 = p[i], x2 = p[i + 128];
    p[i] = x1 * cs - x2 * sn;
    p[i + 128] = x2 * cs + x1 * sn;
}

// ---------------- diffusion time embedding, broadcast into xt[:,H:2H] ----------------
__global__ void timeemb_kernel(const float* __restrict__ ts, float* __restrict__ xt)
{
    int idx = blockIdx.x * blockDim.x + threadIdx.x;
    if (idx >= MTOT * HH) return;
    int m = idx >> 10, j = idx & 1023;
    int b = m / CC;
    float t = ts[b];
    int i = (j < 512) ? j : (j - 512);
    // period = 4e-3 * 1000^(i/512)
    float period = 4e-3f * expf((float)i * (6.907755278982137f / 512.f));
    float ang = 6.283185307179586f * t / period;
    xt[(size_t)m * (2 * HH) + HH + j] = (j < 512) ? sinf(ang) : cosf(ang);
}

// ---------------- gelu(gate)*up, in place into gate ----------------
__global__ void gelumul_kernel(float* __restrict__ gate, const float* __restrict__ up)
{
    int idx = blockIdx.x * blockDim.x + threadIdx.x;
    if (idx >= MTOT * MLPD) return;
    float g = gate[idx];
    float t = tanhf(0.7978845608028654f * (g + 0.044715f * g * g * g));
    gate[idx] = 0.5f * g * (1.f + t) * up[idx];
}

// ---------------- orchestration ----------------
extern "C" void kernel_launch(void* const* d_in, const int* in_sizes, int n_in,
                              void* d_out, int out_size)
{
    const float* noisy   = (const float*)d_in[0];
    const float* tstep   = (const float*)d_in[1];
    const int*   pos_ids = (const int*)d_in[2];
    const float* pk      = (const float*)d_in[3];
    const float* pv      = (const float*)d_in[4];
    const float* in_w    = (const float*)d_in[5];
    const float* in_b    = (const float*)d_in[6];
    const float* t_in_w  = (const float*)d_in[7];
    const float* t_in_b  = (const float*)d_in[8];
    const float* t_out_w = (const float*)d_in[9];
    const float* t_out_b = (const float*)d_in[10];
    const float* out_w   = (const float*)d_in[11];
    const float* out_b   = (const float*)d_in[12];
    const float* fn_w    = (const float*)d_in[13];
    const float* ln1_w   = (const float*)d_in[14];
    const float* q_w     = (const float*)d_in[15];
    const float* k_w     = (const float*)d_in[16];
    const float* v_w     = (const float*)d_in[17];
    const float* o_w     = (const float*)d_in[18];
    const float* ln2_w   = (const float*)d_in[19];
    const float* gate_w  = (const float*)d_in[20];
    const float* up_w    = (const float*)d_in[21];
    const float* down_w  = (const float*)d_in[22];
    float* out = (float*)d_out;

    float *x, *h, *xt, *q, *k, *v, *ao, *s, *gate, *up;
    cudaGetSymbolAddress((void**)&x,    g_x);
    cudaGetSymbolAddress((void**)&h,    g_h);
    cudaGetSymbolAddress((void**)&xt,   g_xt);
    cudaGetSymbolAddress((void**)&q,    g_q);
    cudaGetSymbolAddress((void**)&k,    g_k);
    cudaGetSymbolAddress((void**)&v,    g_v);
    cudaGetSymbolAddress((void**)&ao,   g_ao);
    cudaGetSymbolAddress((void**)&s,    g_s);
    cudaGetSymbolAddress((void**)&gate, g_gate);
    cudaGetSymbolAddress((void**)&up,   g_up);

    // 1. action in-proj into xt[:, 0:H]
    launch_gemm(noisy, in_w, in_b, xt, MTOT, HH, AA, AA, AA, 2 * HH, 1);
    // 2. time embedding broadcast into xt[:, H:2H]
    timeemb_kernel<<<(MTOT * HH + 255) / 256, 256>>>(tstep, xt);
    // 3. fused action-time MLP
    launch_gemm(xt, t_in_w, t_in_b, h, MTOT, HH, 2 * HH, 2 * HH, 2 * HH, HH, 5);  // bias+silu
    launch_gemm(h, t_out_w, t_out_b, x, MTOT, HH, HH, HH, HH, HH, 1);

    for (int l = 0; l < LNUM; l++) {
        const float* qwl = q_w + (size_t)l * (NHH * HD) * HH;
        const float* kwl = k_w + (size_t)l * HD * HH;
        const float* vwl = v_w + (size_t)l * HD * HH;
        const float* owl = o_w + (size_t)l * HH * (NHH * HD);
        const float* gwl = gate_w + (size_t)l * MLPD * HH;
        const float* uwl = up_w + (size_t)l * MLPD * HH;
        const float* dwl = down_w + (size_t)l * HH * MLPD;

        rmsnorm_kernel<<<MTOT, 256>>>(x, ln1_w + l * HH, h);
        launch_gemm(h, qwl, nullptr, q, MTOT, NHH * HD, HH, HH, HH, NHH * HD, 0);
        launch_gemm(h, kwl, nullptr, k, MTOT, HD, HH, HH, HH, HD, 0);
        launch_gemm(h, vwl, nullptr, v, MTOT, HD, HH, HH, HH, HD, 0);
        rope_kernel<<<(MTOT * NHH * 128 + 255) / 256, 256>>>(q, pos_ids, NHH);
        rope_kernel<<<(MTOT * 1 * 128 + 255) / 256, 256>>>(k, pos_ids, 1);
        attn_scores_kernel<<<dim3((TTOT + 63) / 64, 1, BB * NHH), 256>>>(q, pk, k, s, l);
        softmax_kernel<<<BB * NHH * CC, 256>>>(s);
        attn_av_kernel<<<dim3(HD / 64, 1, BB * NHH), 256>>>(s, pv, v, ao, l);
        launch_gemm(ao, owl, nullptr, x, MTOT, HH, NHH * HD, NHH * HD, NHH * HD, HH, 2);  // residual
        rmsnorm_kernel<<<MTOT, 256>>>(x, ln2_w + l * HH, h);
        launch_gemm(h, gwl, nullptr, gate, MTOT, MLPD, HH, HH, HH, MLPD, 0);
        launch_gemm(h, uwl, nullptr, up, MTOT, MLPD, HH, HH, HH, MLPD, 0);
        gelumul_kernel<<<(MTOT * MLPD + 255) / 256, 256>>>(gate, up);
        launch_gemm(gate, dwl, nullptr, x, MTOT, HH, MLPD, MLPD, MLPD, HH, 2);  // residual
    }

    rmsnorm_kernel<<<MTOT, 256>>>(x, fn_w, h);
    launch_gemm(h, out_w, out_b, out, MTOT, AA, HH, HH, HH, AA, 1);
}

// round 2
// speedup vs baseline: 2.1183x; 2.1183x over previous
#include <cuda_runtime.h>
#include <cuda_bf16.h>
#include <cstdint>

#define LNUM 18
#define BB 8
#define CC 50
#define AA 32
#define HH 1024
#define NHH 8
#define HD 256
#define PP 800
#define MLPD 4096
#define MTOT 400
#define TTOT 850
#define TP 896      // padded t (14*64)
#define CP 64       // padded c

// ---------------- scratch (device globals; zero-initialized; no allocation) ----------------
__device__ __align__(256) float g_x[MTOT*HH];
__device__ __align__(256) float g_h[MTOT*HH];
__device__ __align__(256) float g_xt[MTOT*2*HH];
__device__ __align__(256) float g_q[MTOT*NHH*HD];
__device__ __align__(256) float g_k[MTOT*HD];
__device__ __align__(256) float g_v[MTOT*HD];
__device__ __align__(256) float g_ao[MTOT*NHH*HD];
__device__ __align__(256) float g_s[BB*NHH*CP*TP];
__device__ __align__(256) float g_gate[MTOT*MLPD];
__device__ __align__(256) float g_up[MTOT*MLPD];
__device__ __align__(256) __nv_bfloat16 g_qh[BB*NHH*CP*HD];
__device__ __align__(256) __nv_bfloat16 g_ql[BB*NHH*CP*HD];
__device__ __align__(256) __nv_bfloat16 g_kh[BB*TP*HD];
__device__ __align__(256) __nv_bfloat16 g_kl[BB*TP*HD];
__device__ __align__(256) __nv_bfloat16 g_vh[BB*TP*HD];
__device__ __align__(256) __nv_bfloat16 g_vl[BB*TP*HD];
__device__ __align__(256) __nv_bfloat16 g_sh[BB*NHH*CP*TP];
__device__ __align__(256) __nv_bfloat16 g_sl[BB*NHH*CP*TP];

// ---------------- helpers ----------------
__device__ __forceinline__ unsigned su32(const void* p){ return (unsigned)__cvta_generic_to_shared(p); }
__device__ __forceinline__ int swz(int r, int cb){ return r*128 + (cb ^ ((r&7)<<4)); }

__device__ __forceinline__ void ldsm4(unsigned& a,unsigned& b,unsigned& c,unsigned& d, unsigned addr){
  asm volatile("ldmatrix.sync.aligned.m8n8.x4.shared.b16 {%0,%1,%2,%3},[%4];"
    :"=r"(a),"=r"(b),"=r"(c),"=r"(d):"r"(addr));
}
__device__ __forceinline__ void ldsm4t(unsigned& a,unsigned& b,unsigned& c,unsigned& d, unsigned addr){
  asm volatile("ldmatrix.sync.aligned.m8n8.x4.trans.shared.b16 {%0,%1,%2,%3},[%4];"
    :"=r"(a),"=r"(b),"=r"(c),"=r"(d):"r"(addr));
}
__device__ __forceinline__ void mma16816(float* c, const unsigned* a, unsigned b0, unsigned b1){
  asm volatile("mma.sync.aligned.m16n8k16.row.col.f32.bf16.bf16.f32 {%0,%1,%2,%3},{%4,%5,%6,%7},{%8,%9},{%0,%1,%2,%3};"
    :"+f"(c[0]),"+f"(c[1]),"+f"(c[2]),"+f"(c[3])
    :"r"(a[0]),"r"(a[1]),"r"(a[2]),"r"(a[3]),"r"(b0),"r"(b1));
}

__device__ __forceinline__ void split1(float x, unsigned short& h, unsigned short& l){
  __nv_bfloat16 bh = __float2bfloat16_rn(x);
  h = __bfloat16_as_ushort(bh);
  l = __bfloat16_as_ushort(__float2bfloat16_rn(x - __bfloat162float(bh)));
}

__device__ __forceinline__ float blk_reduce(float v, bool ismax) {
    __shared__ float sh[8];
    int lane = threadIdx.x & 31, wid = threadIdx.x >> 5;
    #pragma unroll
    for (int o = 16; o > 0; o >>= 1) {
        float w = __shfl_xor_sync(0xffffffffu, v, o);
        v = ismax ? fmaxf(v, w) : (v + w);
    }
    if (lane == 0) sh[wid] = v;
    __syncthreads();
    if (threadIdx.x == 0) {
        float r = sh[0];
        int nw = (blockDim.x + 31) >> 5;
        for (int i = 1; i < nw; i++) r = ismax ? fmaxf(r, sh[i]) : (r + sh[i]);
        sh[0] = r;
    }
    __syncthreads();
    float r = sh[0];
    __syncthreads();
    return r;
}

// ---------------- weight GEMM: C[M,N] = A[M,K] @ B[N,K]^T via bf16 hi/lo split mma ----------------
// EPI bit0: +bias, bit1: += C_old, bit2: silu
template<int EPI>
__global__ void __launch_bounds__(256) wgemm(
  const float* __restrict__ A, const float* __restrict__ B,
  const float* __restrict__ bias, float* __restrict__ C,
  int M, int N, int K, int lda, int ldb, int ldc)
{
  __shared__ char sm[49152];
  char* sAh = sm;            // 128 rows * 128B
  char* sAl = sm + 16384;
  char* sBh = sm + 32768;    // 64 rows * 128B
  char* sBl = sm + 40960;
  int tid = threadIdx.x, lane = tid & 31, warp = tid >> 5;
  int m0 = blockIdx.y * 128, n0 = blockIdx.x * 64;
  int wm = (warp >> 1) * 32, wn = (warp & 1) * 32;

  float acc[2][4][4];
  #pragma unroll
  for (int i=0;i<2;i++)
    #pragma unroll
    for (int j=0;j<4;j++)
      #pragma unroll
      for (int e=0;e<4;e++) acc[i][j][e]=0.f;

  int ar = tid >> 4, ac4 = tid & 15;
  for (int k0 = 0; k0 < K; k0 += 64) {
    #pragma unroll
    for (int rr = 0; rr < 8; rr++) {
      int r = ar + rr*16;
      int gm = m0 + r, gk = k0 + ac4*4;
      float4 v = make_float4(0.f,0.f,0.f,0.f);
      if (gm < M && gk < K) v = *(const float4*)(A + (size_t)gm*lda + gk);
      unsigned short h0,l0,h1,l1,h2,l2,h3,l3;
      split1(v.x,h0,l0); split1(v.y,h1,l1); split1(v.z,h2,l2); split1(v.w,h3,l3);
      uint2 ph = make_uint2((unsigned)h0|((unsigned)h1<<16), (unsigned)h2|((unsigned)h3<<16));
      uint2 pl = make_uint2((unsigned)l0|((unsigned)l1<<16), (unsigned)l2|((unsigned)l3<<16));
      int off = swz(r, ac4*8);
      *(uint2*)(sAh + off) = ph;
      *(uint2*)(sAl + off) = pl;
    }
    #pragma unroll
    for (int rr = 0; rr < 4; rr++) {
      int r = ar + rr*16;
      int gn = n0 + r, gk = k0 + ac4*4;
      float4 v = make_float4(0.f,0.f,0.f,0.f);
      if (gn < N && gk < K) v = *(const float4*)(B + (size_t)gn*ldb + gk);
      unsigned short h0,l0,h1,l1,h2,l2,h3,l3;
      split1(v.x,h0,l0); split1(v.y,h1,l1); split1(v.z,h2,l2); split1(v.w,h3,l3);
      uint2 ph = make_uint2((unsigned)h0|((unsigned)h1<<16), (unsigned)h2|((unsigned)h3<<16));
      uint2 pl = make_uint2((unsigned)l0|((unsigned)l1<<16), (unsigned)l2|((unsigned)l3<<16));
      int off = swz(r, ac4*8);
      *(uint2*)(sBh + off) = ph;
      *(uint2*)(sBl + off) = pl;
    }
    __syncthreads();
    #pragma unroll
    for (int kk = 0; kk < 4; kk++) {
      unsigned Ah[2][4], Al[2][4], Bh[4][2], Bl[4][2];
      #pragma unroll
      for (int mt = 0; mt < 2; mt++) {
        int r = wm + mt*16 + (lane & 15);
        int cb = kk*32 + ((lane >> 4) << 4);
        int off = swz(r, cb);
        ldsm4(Ah[mt][0],Ah[mt][1],Ah[mt][2],Ah[mt][3], su32(sAh + off));
        ldsm4(Al[mt][0],Al[mt][1],Al[mt][2],Al[mt][3], su32(sAl + off));
      }
      #pragma unroll
      for (int p = 0; p < 2; p++) {
        int r = wn + p*16 + (lane & 15);
        int cb = kk*32 + ((lane >> 4) << 4);
        int off = swz(r, cb);
        unsigned r0,r1,r2,r3;
        ldsm4(r0,r1,r2,r3, su32(sBh + off));
        Bh[p*2][0]=r0; Bh[p*2][1]=r2; Bh[p*2+1][0]=r1; Bh[p*2+1][1]=r3;
        ldsm4(r0,r1,r2,r3, su32(sBl + off));
        Bl[p*2][0]=r0; Bl[p*2][1]=r2; Bl[p*2+1][0]=r1; Bl[p*2+1][1]=r3;
      }
      #pragma unroll
      for (int mt = 0; mt < 2; mt++)
        #pragma unroll
        for (int ns = 0; ns < 4; ns++) {
          mma16816(acc[mt][ns], Ah[mt], Bh[ns][0], Bh[ns][1]);
          mma16816(acc[mt][ns], Ah[mt], Bl[ns][0], Bl[ns][1]);
          mma16816(acc[mt][ns], Al[mt], Bh[ns][0], Bh[ns][1]);
        }
    }
    __syncthreads();
  }
  #pragma unroll
  for (int mt = 0; mt < 2; mt++)
    #pragma unroll
    for (int ns = 0; ns < 4; ns++) {
      int row = m0 + wm + mt*16 + (lane >> 2);
      int col = n0 + wn + ns*8 + (lane & 3)*2;
      #pragma unroll
      for (int e = 0; e < 4; e++) {
        int rr = row + ((e >= 2) ? 8 : 0);
        int cc = col + (e & 1);
        if (rr < M && cc < N) {
          float v = acc[mt][ns][e];
          if (EPI & 1) v += bias[cc];
          if (EPI & 2) v += C[(size_t)rr*ldc + cc];
          if (EPI & 4) v = v / (1.f + expf(-v));
          C[(size_t)rr*ldc + cc] = v;
        }
      }
    }
}

static void launch_gemm(const float* A, const float* B, const float* bias, float* C,
                        int M, int N, int K, int lda, int ldb, int ldc, int epi)
{
  dim3 grid((N + 63)/64, (M + 127)/128);
  switch (epi) {
    case 0: wgemm<0><<<grid,256>>>(A,B,bias,C,M,N,K,lda,ldb,ldc); break;
    case 1: wgemm<1><<<grid,256>>>(A,B,bias,C,M,N,K,lda,ldb,ldc); break;
    case 2: wgemm<2><<<grid,256>>>(A,B,bias,C,M,N,K,lda,ldb,ldc); break;
    case 5: wgemm<5><<<grid,256>>>(A,B,bias,C,M,N,K,lda,ldb,ldc); break;
  }
}

// ---------------- attention scores: S[z][c][t] = qhat[z,c,:] . Kcat[b,t,:] (pre-scaled q) ----------------
__global__ void __launch_bounds__(128) attn_scores(
  const __nv_bfloat16* __restrict__ qh, const __nv_bfloat16* __restrict__ ql,
  const __nv_bfloat16* __restrict__ kh, const __nv_bfloat16* __restrict__ kl,
  float* __restrict__ S)
{
  __shared__ char sm[32768];
  char* sAh = sm; char* sAl = sm + 8192; char* sBh = sm + 16384; char* sBl = sm + 24576;
  int z = blockIdx.z, b = z >> 3;
  int t0 = blockIdx.x * 64;
  int tid = threadIdx.x, lane = tid & 31, warp = tid >> 5;
  int wm = (warp >> 1) * 32, wn = (warp & 1) * 32;
  const __nv_bfloat16* Agh = qh + (size_t)z*CP*HD;
  const __nv_bfloat16* Agl = ql + (size_t)z*CP*HD;
  const __nv_bfloat16* Bgh = kh + ((size_t)b*TP + t0)*HD;
  const __nv_bfloat16* Bgl = kl + ((size_t)b*TP + t0)*HD;

  float acc[2][4][4];
  #pragma unroll
  for (int i=0;i<2;i++)
    #pragma unroll
    for (int j=0;j<4;j++)
      #pragma unroll
      for (int e=0;e<4;e++) acc[i][j][e]=0.f;

  int lr = tid >> 3, lc = tid & 7;
  for (int k0 = 0; k0 < HD; k0 += 64) {
    #pragma unroll
    for (int rr = 0; rr < 4; rr++) {
      int r = lr + rr*16;
      int off = swz(r, lc*16);
      *(uint4*)(sAh + off) = *(const uint4*)(Agh + (size_t)r*HD + k0 + lc*8);
      *(uint4*)(sAl + off) = *(const uint4*)(Agl + (size_t)r*HD + k0 + lc*8);
      *(uint4*)(sBh + off) = *(const uint4*)(Bgh + (size_t)r*HD + k0 + lc*8);
      *(uint4*)(sBl + off) = *(const uint4*)(Bgl + (size_t)r*HD + k0 + lc*8);
    }
    __syncthreads();
    #pragma unroll
    for (int kk = 0; kk < 4; kk++) {
      unsigned Ah[2][4], Al[2][4], Bh[4][2], Bl[4][2];
      #pragma unroll
      for (int mt = 0; mt < 2; mt++) {
        int r = wm + mt*16 + (lane & 15);
        int cb = kk*32 + ((lane >> 4) << 4);
        int off = swz(r, cb);
        ldsm4(Ah[mt][0],Ah[mt][1],Ah[mt][2],Ah[mt][3], su32(sAh + off));
        ldsm4(Al[mt][0],Al[mt][1],Al[mt][2],Al[mt][3], su32(sAl + off));
      }
      #pragma unroll
      for (int p = 0; p < 2; p++) {
        int r = wn + p*16 + (lane & 15);
        int cb = kk*32 + ((lane >> 4) << 4);
        int off = swz(r, cb);
        unsigned r0,r1,r2,r3;
        ldsm4(r0,r1,r2,r3, su32(sBh + off));
        Bh[p*2][0]=r0; Bh[p*2][1]=r2; Bh[p*2+1][0]=r1; Bh[p*2+1][1]=r3;
        ldsm4(r0,r1,r2,r3, su32(sBl + off));
        Bl[p*2][0]=r0; Bl[p*2][1]=r2; Bl[p*2+1][0]=r1; Bl[p*2+1][1]=r3;
      }
      #pragma unroll
      for (int mt = 0; mt < 2; mt++)
        #pragma unroll
        for (int ns = 0; ns < 4; ns++) {
          mma16816(acc[mt][ns], Ah[mt], Bh[ns][0], Bh[ns][1]);
          mma16816(acc[mt][ns], Ah[mt], Bl[ns][0], Bl[ns][1]);
          mma16816(acc[mt][ns], Al[mt], Bh[ns][0], Bh[ns][1]);
        }
    }
    __syncthreads();
  }
  float* Sb = S + (size_t)z*CP*TP;
  #pragma unroll
  for (int mt = 0; mt < 2; mt++)
    #pragma unroll
    for (int ns = 0; ns < 4; ns++) {
      int row = wm + mt*16 + (lane >> 2);
      int col = t0 + wn + ns*8 + (lane & 3)*2;
      Sb[(size_t)row*TP + col]          = acc[mt][ns][0];
      Sb[(size_t)row*TP + col + 1]      = acc[mt][ns][1];
      Sb[(size_t)(row+8)*TP + col]      = acc[mt][ns][2];
      Sb[(size_t)(row+8)*TP + col + 1]  = acc[mt][ns][3];
    }
}

// ---------------- softmax over t, fused bf16 hi/lo output ----------------
__global__ void __launch_bounds__(256) softmax_kernel(
  const float* __restrict__ S, __nv_bfloat16* __restrict__ Sh, __nv_bfloat16* __restrict__ Sl)
{
  int row = blockIdx.x;            // 0..BB*NHH*CC-1
  int z = row / CC, c = row % CC;
  const float* s = S + ((size_t)z*CP + c)*TP;
  float vals[4];
  float mx = -1e30f;
  #pragma unroll
  for (int ii = 0; ii < 4; ii++) {
    int j = threadIdx.x + ii*256;
    vals[ii] = (j < TTOT) ? s[j] : -1e30f;
    mx = fmaxf(mx, vals[ii]);
  }
  mx = blk_reduce(mx, true);
  float sum = 0.f;
  #pragma unroll
  for (int ii = 0; ii < 4; ii++) {
    int j = threadIdx.x + ii*256;
    if (j < TTOT) { vals[ii] = expf(vals[ii] - mx); sum += vals[ii]; }
  }
  sum = blk_reduce(sum, false);
  float inv = 1.f / sum;
  size_t base = ((size_t)z*CP + c)*TP;
  #pragma unroll
  for (int ii = 0; ii < 4; ii++) {
    int j = threadIdx.x + ii*256;
    if (j < TTOT) {
      float p = vals[ii] * inv;
      unsigned short h, l;
      split1(p, h, l);
      Sh[base + j] = __ushort_as_bfloat16(h);
      Sl[base + j] = __ushort_as_bfloat16(l);
    }
  }
}

// ---------------- AV: O[b,c,n,d] = sum_t P[z,c,t] * Vcat[b,t,d] ----------------
__global__ void __launch_bounds__(128) attn_av(
  const __nv_bfloat16* __restrict__ sh_, const __nv_bfloat16* __restrict__ sl_,
  const __nv_bfloat16* __restrict__ vh, const __nv_bfloat16* __restrict__ vl,
  float* __restrict__ O)
{
  __shared__ char sm[32768];
  char* sAh = sm; char* sAl = sm + 8192; char* sBh = sm + 16384; char* sBl = sm + 24576;
  int z = blockIdx.z, b = z >> 3, n = z & 7;
  int d0 = blockIdx.x * 64;
  int tid = threadIdx.x, lane = tid & 31, warp = tid >> 5;
  int wm = (warp >> 1) * 32, wn = (warp & 1) * 32;
  const __nv_bfloat16* Agh = sh_ + (size_t)z*CP*TP;
  const __nv_bfloat16* Agl = sl_ + (size_t)z*CP*TP;
  const __nv_bfloat16* Bgh = vh + (size_t)b*TP*HD + d0;
  const __nv_bfloat16* Bgl = vl + (size_t)b*TP*HD + d0;

  float acc[2][4][4];
  #pragma unroll
  for (int i=0;i<2;i++)
    #pragma unroll
    for (int j=0;j<4;j++)
      #pragma unroll
      for (int e=0;e<4;e++) acc[i][j][e]=0.f;

  int lr = tid >> 3, lc = tid & 7;
  for (int k0 = 0; k0 < TP; k0 += 64) {
    #pragma unroll
    for (int rr = 0; rr < 4; rr++) {
      int r = lr + rr*16;
      int off = swz(r, lc*16);
      *(uint4*)(sAh + off) = *(const uint4*)(Agh + (size_t)r*TP + k0 + lc*8);
      *(uint4*)(sAl + off) = *(const uint4*)(Agl + (size_t)r*TP + k0 + lc*8);
      // B rows are t (reduction dim), natural [t][d] layout
      *(uint4*)(sBh + off) = *(const uint4*)(Bgh + (size_t)(k0 + r)*HD + lc*8);
      *(uint4*)(sBl + off) = *(const uint4*)(Bgl + (size_t)(k0 + r)*HD + lc*8);
    }
    __syncthreads();
    #pragma unroll
    for (int kk = 0; kk < 4; kk++) {
      unsigned Ah[2][4], Al[2][4], Bh[4][2], Bl[4][2];
      #pragma unroll
      for (int mt = 0; mt < 2; mt++) {
        int r = wm + mt*16 + (lane & 15);
        int cb = kk*32 + ((lane >> 4) << 4);
        int off = swz(r, cb);
        ldsm4(Ah[mt][0],Ah[mt][1],Ah[mt][2],Ah[mt][3], su32(sAh + off));
        ldsm4(Al[mt][0],Al[mt][1],Al[mt][2],Al[mt][3], su32(sAl + off));
      }
      // B via ldmatrix.trans: rows = t within this k16, chunks = d
      #pragma unroll
      for (int p = 0; p < 2; p++) {
        int r = kk*16 + (lane & 15);
        int cb = (wn + p*16)*2 + ((lane >> 4) << 4);
        int off = swz(r, cb);
        unsigned r0,r1,r2,r3;
        ldsm4t(r0,r1,r2,r3, su32(sBh + off));
        Bh[p*2][0]=r0; Bh[p*2][1]=r1; Bh[p*2+1][0]=r2; Bh[p*2+1][1]=r3;
        ldsm4t(r0,r1,r2,r3, su32(sBl + off));
        Bl[p*2][0]=r0; Bl[p*2][1]=r1; Bl[p*2+1][0]=r2; Bl[p*2+1][1]=r3;
      }
      #pragma unroll
      for (int mt = 0; mt < 2; mt++)
        #pragma unroll
        for (int ns = 0; ns < 4; ns++) {
          mma16816(acc[mt][ns], Ah[mt], Bh[ns][0], Bh[ns][1]);
          mma16816(acc[mt][ns], Ah[mt], Bl[ns][0], Bl[ns][1]);
          mma16816(acc[mt][ns], Al[mt], Bh[ns][0], Bh[ns][1]);
        }
    }
    __syncthreads();
  }
  #pragma unroll
  for (int mt = 0; mt < 2; mt++)
    #pragma unroll
    for (int ns = 0; ns < 4; ns++) {
      int c = wm + mt*16 + (lane >> 2);
      int d = d0 + wn + ns*8 + (lane & 3)*2;
      #pragma unroll
      for (int e = 0; e < 4; e++) {
        int cc = c + ((e >= 2) ? 8 : 0);
        int dd = d + (e & 1);
        if (cc < CC)
          O[((size_t)(b*CC + cc))*(NHH*HD) + n*HD + dd] = acc[mt][ns][e];
      }
    }
}

// ---------------- q: rope + scale + split -> [b][n][CP][HD] ----------------
__global__ void qconv_kernel(const float* __restrict__ q, const int* __restrict__ pos,
                             __nv_bfloat16* __restrict__ qh, __nv_bfloat16* __restrict__ ql)
{
  int idx = blockIdx.x * blockDim.x + threadIdx.x;
  if (idx >= MTOT*NHH*128) return;
  int i = idx & 127;
  int mn = idx >> 7;
  int n = mn & 7, m = mn >> 3;
  int b = m / CC, c = m % CC;
  const float* p = q + (size_t)m*(NHH*HD) + n*HD;
  float x1 = p[i], x2 = p[i + 128];
  float ang = (float)pos[c] * expf(-(float)i * (9.210340371976184f/128.f));
  float sn, cs; sincosf(ang, &sn, &cs);
  float o1 = (x1*cs - x2*sn) * 0.0625f;
  float o2 = (x2*cs + x1*sn) * 0.0625f;
  size_t dst = ((size_t)(b*NHH + n)*CP + c)*HD;
  unsigned short h, l;
  split1(o1, h, l); qh[dst+i] = __ushort_as_bfloat16(h); ql[dst+i] = __ushort_as_bfloat16(l);
  split1(o2, h, l); qh[dst+i+128] = __ushort_as_bfloat16(h); ql[dst+i+128] = __ushort_as_bfloat16(l);
}

// ---------------- Kcat: prefix convert + rope(new k) + split -> [b][TP][HD] ----------------
__global__ void kconv_kernel(const float* __restrict__ pk, const float* __restrict__ knew,
                             const int* __restrict__ pos,
                             __nv_bfloat16* __restrict__ kh, __nv_bfloat16* __restrict__ kl, int layer)
{
  int idx = blockIdx.x * blockDim.x + threadIdx.x;
  if (idx >= BB*TTOT*HD) return;
  int d = idx & 255;
  int bt = idx >> 8;
  int t = bt % TTOT, b = bt / TTOT;
  size_t dst = ((size_t)b*TP + t)*HD;
  unsigned short h, l;
  if (t < PP) {
    float x = pk[(((size_t)layer*BB + b)*PP + t)*HD + d];
    split1(x, h, l);
    kh[dst+d] = __ushort_as_bfloat16(h); kl[dst+d] = __ushort_as_bfloat16(l);
  } else if (d < 128) {
    int c = t - PP;
    const float* p = knew + (size_t)(b*CC + c)*HD;
    float x1 = p[d], x2 = p[d + 128];
    float ang = (float)pos[c] * expf(-(float)d * (9.210340371976184f/128.f));
    float sn, cs; sincosf(ang, &sn, &cs);
    float o1 = x1*cs - x2*sn;
    float o2 = x2*cs + x1*sn;
    split1(o1, h, l); kh[dst+d] = __ushort_as_bfloat16(h); kl[dst+d] = __ushort_as_bfloat16(l);
    split1(o2, h, l); kh[dst+d+128] = __ushort_as_bfloat16(h); kl[dst+d+128] = __ushort_as_bfloat16(l);
  }
}

// ---------------- Vcat: convert + split -> [b][TP][HD] ----------------
__global__ void vconv_kernel(const float* __restrict__ pv, const float* __restrict__ vnew,
                             __nv_bfloat16* __restrict__ vh, __nv_bfloat16* __restrict__ vl, int layer)
{
  int idx = blockIdx.x * blockDim.x + threadIdx.x;
  if (idx >= BB*TTOT*HD) return;
  int d = idx & 255;
  int bt = idx >> 8;
  int t = bt % TTOT, b = bt / TTOT;
  float x = (t < PP) ? pv[(((size_t)layer*BB + b)*PP + t)*HD + d]
                     : vnew[(size_t)(b*CC + (t - PP))*HD + d];
  unsigned short h, l;
  split1(x, h, l);
  size_t dst = ((size_t)b*TP + t)*HD;
  vh[dst+d] = __ushort_as_bfloat16(h);
  vl[dst+d] = __ushort_as_bfloat16(l);
}

// ---------------- rmsnorm ----------------
__global__ void __launch_bounds__(256) rmsnorm_kernel(
  const float* __restrict__ x, const float* __restrict__ w, float* __restrict__ out)
{
  int row = blockIdx.x;
  const float* xr = x + (size_t)row*HH;
  float ss = 0.f;
  for (int j = threadIdx.x; j < HH; j += 256) { float v = xr[j]; ss += v*v; }
  ss = blk_reduce(ss, false);
  float sc = rsqrtf(ss * (1.f/HH) + 1e-6f);
  for (int j = threadIdx.x; j < HH; j += 256)
    out[(size_t)row*HH + j] = xr[j] * sc * w[j];
}

// ---------------- time embedding ----------------
__global__ void timeemb_kernel(const float* __restrict__ ts, float* __restrict__ xt)
{
  int idx = blockIdx.x * blockDim.x + threadIdx.x;
  if (idx >= MTOT*HH) return;
  int m = idx >> 10, j = idx & 1023;
  int b = m / CC;
  float t = ts[b];
  int i = (j < 512) ? j : (j - 512);
  float period = 4e-3f * expf((float)i * (6.907755278982137f/512.f));
  float ang = 6.283185307179586f * t / period;
  xt[(size_t)m*(2*HH) + HH + j] = (j < 512) ? sinf(ang) : cosf(ang);
}

// ---------------- gelu(gate)*up ----------------
__global__ void gelumul_kernel(float* __restrict__ gate, const float* __restrict__ up)
{
  int idx = blockIdx.x * blockDim.x + threadIdx.x;
  if (idx >= MTOT*MLPD) return;
  float g = gate[idx];
  float t = tanhf(0.7978845608028654f * (g + 0.044715f*g*g*g));
  gate[idx] = 0.5f * g * (1.f + t) * up[idx];
}

// ---------------- orchestration ----------------
extern "C" void kernel_launch(void* const* d_in, const int* in_sizes, int n_in,
                              void* d_out, int out_size)
{
  const float* noisy   = (const float*)d_in[0];
  const float* tstep   = (const float*)d_in[1];
  const int*   pos_ids = (const int*)d_in[2];
  const float* pk      = (const float*)d_in[3];
  const float* pv      = (const float*)d_in[4];
  const float* in_w    = (const float*)d_in[5];
  const float* in_b    = (const float*)d_in[6];
  const float* t_in_w  = (const float*)d_in[7];
  const float* t_in_b  = (const float*)d_in[8];
  const float* t_out_w = (const float*)d_in[9];
  const float* t_out_b = (const float*)d_in[10];
  const float* out_w   = (const float*)d_in[11];
  const float* out_b   = (const float*)d_in[12];
  const float* fn_w    = (const float*)d_in[13];
  const float* ln1_w   = (const float*)d_in[14];
  const float* q_w     = (const float*)d_in[15];
  const float* k_w     = (const float*)d_in[16];
  const float* v_w     = (const float*)d_in[17];
  const float* o_w     = (const float*)d_in[18];
  const float* ln2_w   = (const float*)d_in[19];
  const float* gate_w  = (const float*)d_in[20];
  const float* up_w    = (const float*)d_in[21];
  const float* down_w  = (const float*)d_in[22];
  float* out = (float*)d_out;

  float *x,*h,*xt,*q,*k,*v,*ao,*s,*gate,*up;
  __nv_bfloat16 *qh,*ql,*kh,*kl,*vh,*vl,*sh,*sl;
  cudaGetSymbolAddress((void**)&x, g_x);
  cudaGetSymbolAddress((void**)&h, g_h);
  cudaGetSymbolAddress((void**)&xt, g_xt);
  cudaGetSymbolAddress((void**)&q, g_q);
  cudaGetSymbolAddress((void**)&k, g_k);
  cudaGetSymbolAddress((void**)&v, g_v);
  cudaGetSymbolAddress((void**)&ao, g_ao);
  cudaGetSymbolAddress((void**)&s, g_s);
  cudaGetSymbolAddress((void**)&gate, g_gate);
  cudaGetSymbolAddress((void**)&up, g_up);
  cudaGetSymbolAddress((void**)&qh, g_qh);
  cudaGetSymbolAddress((void**)&ql, g_ql);
  cudaGetSymbolAddress((void**)&kh, g_kh);
  cudaGetSymbolAddress((void**)&kl, g_kl);
  cudaGetSymbolAddress((void**)&vh, g_vh);
  cudaGetSymbolAddress((void**)&vl, g_vl);
  cudaGetSymbolAddress((void**)&sh, g_sh);
  cudaGetSymbolAddress((void**)&sl, g_sl);

  // prologue
  launch_gemm(noisy, in_w, in_b, xt, MTOT, HH, AA, AA, AA, 2*HH, 1);
  timeemb_kernel<<<(MTOT*HH + 255)/256, 256>>>(tstep, xt);
  launch_gemm(xt, t_in_w, t_in_b, h, MTOT, HH, 2*HH, 2*HH, 2*HH, HH, 5);
  launch_gemm(h, t_out_w, t_out_b, x, MTOT, HH, HH, HH, HH, HH, 1);

  for (int l = 0; l < LNUM; l++) {
    const float* qwl = q_w + (size_t)l*(NHH*HD)*HH;
    const float* kwl = k_w + (size_t)l*HD*HH;
    const float* vwl = v_w + (size_t)l*HD*HH;
    const float* owl = o_w + (size_t)l*HH*(NHH*HD);
    const float* gwl = gate_w + (size_t)l*MLPD*HH;
    const float* uwl = up_w + (size_t)l*MLPD*HH;
    const float* dwl = down_w + (size_t)l*HH*MLPD;

    rmsnorm_kernel<<<MTOT, 256>>>(x, ln1_w + l*HH, h);
    launch_gemm(h, qwl, nullptr, q, MTOT, NHH*HD, HH, HH, HH, NHH*HD, 0);
    launch_gemm(h, kwl, nullptr, k, MTOT, HD, HH, HH, HH, HD, 0);
    launch_gemm(h, vwl, nullptr, v, MTOT, HD, HH, HH, HH, HD, 0);
    qconv_kernel<<<(MTOT*NHH*128 + 255)/256, 256>>>(q, pos_ids, qh, ql);
    kconv_kernel<<<(BB*TTOT*HD + 255)/256, 256>>>(pk, k, pos_ids, kh, kl, l);
    vconv_kernel<<<(BB*TTOT*HD + 255)/256, 256>>>(pv, v, vh, vl, l);
    attn_scores<<<dim3(TP/64, 1, BB*NHH), 128>>>(qh, ql, kh, kl, s);
    softmax_kernel<<<BB*NHH*CC, 256>>>(s, sh, sl);
    attn_av<<<dim3(HD/64, 1, BB*NHH), 128>>>(sh, sl, vh, vl, ao);
    launch_gemm(ao, owl, nullptr, x, MTOT, HH, NHH*HD, NHH*HD, NHH*HD, HH, 2);
    rmsnorm_kernel<<<MTOT, 256>>>(x, ln2_w + l*HH, h);
    launch_gemm(h, gwl, nullptr, gate, MTOT, MLPD, HH, HH, HH, MLPD, 0);
    launch_gemm(h, uwl, nullptr, up, MTOT, MLPD, HH, HH, HH, MLPD, 0);
    gelumul_kernel<<<(MTOT*MLPD + 255)/256, 256>>>(gate, up);
    launch_gemm(gate, dwl, nullptr, x, MTOT, HH, MLPD, MLPD, MLPD, HH, 2);
  }

  rmsnorm_kernel<<<MTOT, 256>>>(x, fn_w, h);
  launch_gemm(h, out_w, out_b, out, MTOT, AA, HH, HH, HH, AA, 1);
}

// round 3
// speedup vs baseline: 2.6647x; 1.2580x over previous
#include <cuda_runtime.h>
#include <cuda_bf16.h>
#include <cstdint>

#define LNUM 18
#define BB 8
#define CC 50
#define AA 32
#define HH 1024
#define NHH 8
#define HD 256
#define PP 800
#define MLPD 4096
#define MTOT 400
#define TTOT 850
#define TP 896
#define CP 64
#define MPAD 512
#define SMEM_GEMM (96*1024)

typedef __nv_bfloat16 bf16;

// ---------------- fp32 scratch ----------------
__device__ __align__(256) float g_x[MTOT*HH];
__device__ __align__(256) float g_q[MTOT*NHH*HD];
__device__ __align__(256) float g_k[MTOT*HD];
__device__ __align__(256) float g_v[MTOT*HD];
__device__ __align__(256) float g_s[BB*NHH*CP*TP];
__device__ __align__(256) float g_gate[MTOT*MLPD];
__device__ __align__(256) float g_up[MTOT*MLPD];

// ---------------- bf16 activations (hi/lo), padded to MPAD rows ----------------
__device__ __align__(256) bf16 g_hh[MPAD*HH];
__device__ __align__(256) bf16 g_hl[MPAD*HH];
__device__ __align__(256) bf16 g_xth[MPAD*2*HH];
__device__ __align__(256) bf16 g_xtl[MPAD*2*HH];
__device__ __align__(256) bf16 g_midh[MPAD*MLPD];
__device__ __align__(256) bf16 g_midl[MPAD*MLPD];
__device__ __align__(256) bf16 g_aoh[MPAD*NHH*HD];
__device__ __align__(256) bf16 g_aol[MPAD*NHH*HD];
__device__ __align__(256) bf16 g_nh[MPAD*64];
__device__ __align__(256) bf16 g_nl[MPAD*64];

// ---------------- bf16 attention operands ----------------
__device__ __align__(256) bf16 g_qh[BB*NHH*CP*HD];
__device__ __align__(256) bf16 g_ql[BB*NHH*CP*HD];
__device__ __align__(256) bf16 g_kh[BB*TP*HD];
__device__ __align__(256) bf16 g_kl[BB*TP*HD];
__device__ __align__(256) bf16 g_vh[BB*TP*HD];
__device__ __align__(256) bf16 g_vl[BB*TP*HD];
__device__ __align__(256) bf16 g_sh[BB*NHH*CP*TP];
__device__ __align__(256) bf16 g_sl[BB*NHH*CP*TP];

// ---------------- bf16 weights (hi/lo) ----------------
__device__ bf16 g_qwh[LNUM*2048*1024];
__device__ bf16 g_qwl[LNUM*2048*1024];
__device__ bf16 g_kwh[LNUM*256*1024];
__device__ bf16 g_kwl[LNUM*256*1024];
__device__ bf16 g_vwh[LNUM*256*1024];
__device__ bf16 g_vwl[LNUM*256*1024];
__device__ bf16 g_owh[LNUM*1024*2048];
__device__ bf16 g_owl[LNUM*1024*2048];
__device__ bf16 g_gwh[LNUM*4096*1024];
__device__ bf16 g_gwl[LNUM*4096*1024];
__device__ bf16 g_uwh[LNUM*4096*1024];
__device__ bf16 g_uwl[LNUM*4096*1024];
__device__ bf16 g_dwh[LNUM*1024*4096];
__device__ bf16 g_dwl[LNUM*1024*4096];
__device__ bf16 g_tinh[1024*2048];
__device__ bf16 g_tinl[1024*2048];
__device__ bf16 g_touth[1024*1024];
__device__ bf16 g_toutl[1024*1024];
__device__ bf16 g_outwh[64*1024];
__device__ bf16 g_outwl[64*1024];
__device__ bf16 g_inwh[1024*64];
__device__ bf16 g_inwl[1024*64];

// ---------------- helpers ----------------
__device__ __forceinline__ unsigned su32(const void* p){ return (unsigned)__cvta_generic_to_shared(p); }
__device__ __forceinline__ int swz(int r, int cb){ return r*128 + (cb ^ ((r&7)<<4)); }

__device__ __forceinline__ void ldsm4(unsigned& a,unsigned& b,unsigned& c,unsigned& d, unsigned addr){
  asm volatile("ldmatrix.sync.aligned.m8n8.x4.shared.b16 {%0,%1,%2,%3},[%4];"
    :"=r"(a),"=r"(b),"=r"(c),"=r"(d):"r"(addr));
}
__device__ __forceinline__ void ldsm4t(unsigned& a,unsigned& b,unsigned& c,unsigned& d, unsigned addr){
  asm volatile("ldmatrix.sync.aligned.m8n8.x4.trans.shared.b16 {%0,%1,%2,%3},[%4];"
    :"=r"(a),"=r"(b),"=r"(c),"=r"(d):"r"(addr));
}
__device__ __forceinline__ void mma16816(float* c, const unsigned* a, unsigned b0, unsigned b1){
  asm volatile("mma.sync.aligned.m16n8k16.row.col.f32.bf16.bf16.f32 {%0,%1,%2,%3},{%4,%5,%6,%7},{%8,%9},{%0,%1,%2,%3};"
    :"+f"(c[0]),"+f"(c[1]),"+f"(c[2]),"+f"(c[3])
    :"r"(a[0]),"r"(a[1]),"r"(a[2]),"r"(a[3]),"r"(b0),"r"(b1));
}
__device__ __forceinline__ void split1(float x, unsigned short& h, unsigned short& l){
  __nv_bfloat16 bh = __float2bfloat16_rn(x);
  h = __bfloat16_as_ushort(bh);
  l = __bfloat16_as_ushort(__float2bfloat16_rn(x - __bfloat162float(bh)));
}
__device__ __forceinline__ void cpa16(void* sdst, const void* gsrc){
  unsigned d = su32(sdst);
  asm volatile("cp.async.cg.shared.global [%0],[%1],16;" :: "r"(d),"l"(gsrc));
}

__device__ __forceinline__ float blk_reduce(float v, bool ismax) {
    __shared__ float sh[8];
    int lane = threadIdx.x & 31, wid = threadIdx.x >> 5;
    #pragma unroll
    for (int o = 16; o > 0; o >>= 1) {
        float w = __shfl_xor_sync(0xffffffffu, v, o);
        v = ismax ? fmaxf(v, w) : (v + w);
    }
    if (lane == 0) sh[wid] = v;
    __syncthreads();
    if (threadIdx.x == 0) {
        float r = sh[0];
        int nw = (blockDim.x + 31) >> 5;
        for (int i = 1; i < nw; i++) r = ismax ? fmaxf(r, sh[i]) : (r + sh[i]);
        sh[0] = r;
    }
    __syncthreads();
    float r = sh[0];
    __syncthreads();
    return r;
}

// ---------------- GEMM core: 128x64 tile, bf16 hi/lo 3-term, cp.async 2-stage ----------------
__device__ __forceinline__ void load_stage(char* st,
  const bf16* Ah, const bf16* Al, const bf16* Bh, const bf16* Bl,
  int lda, int ldb, int k0, int tid)
{
  char* sAh = st; char* sAl = st+16384; char* sBh = st+32768; char* sBl = st+40960;
  int r0 = tid>>3, ch = tid&7;
  #pragma unroll
  for(int e=0;e<4;e++){
    int r = r0 + e*32;
    int off = swz(r, ch*16);
    cpa16(sAh+off, Ah + (size_t)r*lda + k0 + ch*8);
    cpa16(sAl+off, Al + (size_t)r*lda + k0 + ch*8);
  }
  #pragma unroll
  for(int e=0;e<2;e++){
    int r = r0 + e*32;
    int off = swz(r, ch*16);
    cpa16(sBh+off, Bh + (size_t)r*ldb + k0 + ch*8);
    cpa16(sBl+off, Bl + (size_t)r*ldb + k0 + ch*8);
  }
}

__device__ __forceinline__ void compute_stage(char* st, float acc[2][4][4], int lane, int wm, int wn)
{
  char* sAh = st; char* sAl = st+16384; char* sBh = st+32768; char* sBl = st+40960;
  #pragma unroll
  for(int kk=0;kk<4;kk++){
    unsigned Ah[2][4], Al[2][4], Bh[4][2], Bl[4][2];
    #pragma unroll
    for(int mt=0;mt<2;mt++){
      int r = wm + mt*16 + (lane & 15);
      int cb = kk*32 + ((lane >> 4) << 4);
      int off = swz(r, cb);
      ldsm4(Ah[mt][0],Ah[mt][1],Ah[mt][2],Ah[mt][3], su32(sAh + off));
      ldsm4(Al[mt][0],Al[mt][1],Al[mt][2],Al[mt][3], su32(sAl + off));
    }
    #pragma unroll
    for(int p=0;p<2;p++){
      int r = wn + p*16 + (lane & 15);
      int cb = kk*32 + ((lane >> 4) << 4);
      int off = swz(r, cb);
      unsigned r0,r1,r2,r3;
      ldsm4(r0,r1,r2,r3, su32(sBh + off));
      Bh[p*2][0]=r0; Bh[p*2][1]=r2; Bh[p*2+1][0]=r1; Bh[p*2+1][1]=r3;
      ldsm4(r0,r1,r2,r3, su32(sBl + off));
      Bl[p*2][0]=r0; Bl[p*2][1]=r2; Bl[p*2+1][0]=r1; Bl[p*2+1][1]=r3;
    }
    #pragma unroll
    for(int mt=0;mt<2;mt++)
      #pragma unroll
      for(int ns=0;ns<4;ns++){
        mma16816(acc[mt][ns], Ah[mt], Bh[ns][0], Bh[ns][1]);
        mma16816(acc[mt][ns], Ah[mt], Bl[ns][0], Bl[ns][1]);
        mma16816(acc[mt][ns], Al[mt], Bh[ns][0], Bh[ns][1]);
      }
  }
}

// EPI bits: 1=bias, 2=residual fp32, 4=silu, 8=store bf16 hi/lo, 16=atomicAdd fp32
template<int EPI>
__device__ __forceinline__ void gemm_core(
  const bf16* Ah, const bf16* Al, const bf16* Bh, const bf16* Bl,
  const float* bias, float* Cf, bf16* Ch, bf16* Cl,
  int M, int N, int K, int lda, int ldb, int ldc, int m0, int n0)
{
  extern __shared__ char smem_dyn[];
  char* st0 = smem_dyn; char* st1 = smem_dyn + 49152;
  int tid = threadIdx.x, lane = tid&31, warp = tid>>5;
  int wm = (warp>>1)*32, wn = (warp&1)*32;
  float acc[2][4][4];
  #pragma unroll
  for(int i=0;i<2;i++)
    #pragma unroll
    for(int j=0;j<4;j++)
      #pragma unroll
      for(int e=0;e<4;e++) acc[i][j][e]=0.f;

  const bf16* Ahp = Ah + (size_t)m0*lda;
  const bf16* Alp = Al + (size_t)m0*lda;
  const bf16* Bhp = Bh + (size_t)n0*ldb;
  const bf16* Blp = Bl + (size_t)n0*ldb;
  int nk = K >> 6;
  load_stage(st0, Ahp, Alp, Bhp, Blp, lda, ldb, 0, tid);
  asm volatile("cp.async.commit_group;\n");
  for(int i=0;i<nk;i++){
    if(i+1 < nk){
      load_stage((i&1)?st0:st1, Ahp, Alp, Bhp, Blp, lda, ldb, (i+1)<<6, tid);
      asm volatile("cp.async.commit_group;\n");
      asm volatile("cp.async.wait_group 1;\n");
    } else {
      asm volatile("cp.async.wait_group 0;\n");
    }
    __syncthreads();
    compute_stage((i&1)?st1:st0, acc, lane, wm, wn);
    __syncthreads();
  }
  #pragma unroll
  for(int mt=0;mt<2;mt++)
    #pragma unroll
    for(int ns=0;ns<4;ns++){
      int row = m0 + wm + mt*16 + (lane>>2);
      int col = n0 + wn + ns*8 + (lane&3)*2;
      #pragma unroll
      for(int e=0;e<4;e++){
        int rr = row + ((e>=2)?8:0);
        int cc = col + (e&1);
        if(rr < M && cc < N){
          float v = acc[mt][ns][e];
          if(EPI&1) v += bias[cc];
          if(EPI&4) v = v/(1.f+expf(-v));
          if(EPI&16){
            atomicAdd(&Cf[(size_t)rr*ldc+cc], v);
          } else if(EPI&8){
            unsigned short h,l; split1(v,h,l);
            Ch[(size_t)rr*ldc+cc] = __ushort_as_bfloat16(h);
            Cl[(size_t)rr*ldc+cc] = __ushort_as_bfloat16(l);
          } else {
            if(EPI&2) v += Cf[(size_t)rr*ldc+cc];
            Cf[(size_t)rr*ldc+cc] = v;
          }
        }
      }
    }
}

template<int EPI>
__global__ void __launch_bounds__(256,2) gemm_bf(
  const bf16* Ah, const bf16* Al, const bf16* Bh, const bf16* Bl,
  const float* bias, float* Cf, bf16* Ch, bf16* Cl,
  int M, int N, int K, int lda, int ldb, int ldc)
{
  size_t kofs = (size_t)blockIdx.z * K;
  gemm_core<EPI>(Ah+kofs, Al+kofs, Bh+kofs, Bl+kofs, bias, Cf, Ch, Cl,
                 M, N, K, lda, ldb, ldc, blockIdx.y*128, blockIdx.x*64);
}

__global__ void __launch_bounds__(256,2) qkv_gemm(
  const bf16* Ah, const bf16* Al,
  const bf16* qwh, const bf16* qwl, const bf16* kwh, const bf16* kwl,
  const bf16* vwh, const bf16* vwl,
  float* q, float* k, float* v, int layer)
{
  int bx = blockIdx.x, m0 = blockIdx.y*128;
  const bf16 *Bh, *Bl; float* C; int n0, ldc;
  if(bx < 32){
    size_t w = (size_t)layer*2048*1024;
    Bh = qwh + w; Bl = qwl + w; C = q; n0 = bx*64; ldc = 2048;
  } else if(bx < 36){
    size_t w = (size_t)layer*256*1024;
    Bh = kwh + w; Bl = kwl + w; C = k; n0 = (bx-32)*64; ldc = 256;
  } else {
    size_t w = (size_t)layer*256*1024;
    Bh = vwh + w; Bl = vwl + w; C = v; n0 = (bx-36)*64; ldc = 256;
  }
  gemm_core<0>(Ah, Al, Bh, Bl, nullptr, C, nullptr, nullptr,
               MTOT, ldc, 1024, 1024, 1024, ldc, m0, n0);
}

__global__ void __launch_bounds__(256,2) gateup_gemm(
  const bf16* Ah, const bf16* Al,
  const bf16* gwh, const bf16* gwl, const bf16* uwh, const bf16* uwl,
  float* gate, float* up, int layer)
{
  size_t w = (size_t)layer*4096*1024;
  const bf16* Bh = blockIdx.z ? (uwh+w) : (gwh+w);
  const bf16* Bl = blockIdx.z ? (uwl+w) : (gwl+w);
  float* C = blockIdx.z ? up : gate;
  gemm_core<0>(Ah, Al, Bh, Bl, nullptr, C, nullptr, nullptr,
               MTOT, 4096, 1024, 1024, 1024, 4096, blockIdx.y*128, blockIdx.x*64);
}

// ---------------- weight conversion ----------------
__global__ void convsplit(const float* __restrict__ s, bf16* __restrict__ h, bf16* __restrict__ l, int n4)
{
  int i = blockIdx.x*blockDim.x + threadIdx.x;
  if(i >= n4) return;
  float4 v = ((const float4*)s)[i];
  unsigned short h0,l0,h1,l1,h2,l2,h3,l3;
  split1(v.x,h0,l0); split1(v.y,h1,l1); split1(v.z,h2,l2); split1(v.w,h3,l3);
  ((uint2*)h)[i] = make_uint2((unsigned)h0|((unsigned)h1<<16), (unsigned)h2|((unsigned)h3<<16));
  ((uint2*)l)[i] = make_uint2((unsigned)l0|((unsigned)l1<<16), (unsigned)l2|((unsigned)l3<<16));
}

__global__ void padconv32(const float* __restrict__ s, bf16* __restrict__ h, bf16* __restrict__ l, int rows)
{
  int i = blockIdx.x*blockDim.x + threadIdx.x;
  if(i >= rows*32) return;
  int r = i >> 5, c = i & 31;
  unsigned short hh, ll;
  split1(s[i], hh, ll);
  h[r*64+c] = __ushort_as_bfloat16(hh);
  l[r*64+c] = __ushort_as_bfloat16(ll);
}

// ---------------- attention (round-2, proven) ----------------
__global__ void __launch_bounds__(128) attn_scores(
  const bf16* __restrict__ qh, const bf16* __restrict__ ql,
  const bf16* __restrict__ kh, const bf16* __restrict__ kl,
  float* __restrict__ S)
{
  __shared__ char sm[32768];
  char* sAh = sm; char* sAl = sm + 8192; char* sBh = sm + 16384; char* sBl = sm + 24576;
  int z = blockIdx.z, b = z >> 3;
  int t0 = blockIdx.x * 64;
  int tid = threadIdx.x, lane = tid & 31, warp = tid >> 5;
  int wm = (warp >> 1) * 32, wn = (warp & 1) * 32;
  const bf16* Agh = qh + (size_t)z*CP*HD;
  const bf16* Agl = ql + (size_t)z*CP*HD;
  const bf16* Bgh = kh + ((size_t)b*TP + t0)*HD;
  const bf16* Bgl = kl + ((size_t)b*TP + t0)*HD;

  float acc[2][4][4];
  #pragma unroll
  for (int i=0;i<2;i++)
    #pragma unroll
    for (int j=0;j<4;j++)
      #pragma unroll
      for (int e=0;e<4;e++) acc[i][j][e]=0.f;

  int lr = tid >> 3, lc = tid & 7;
  for (int k0 = 0; k0 < HD; k0 += 64) {
    #pragma unroll
    for (int rr = 0; rr < 4; rr++) {
      int r = lr + rr*16;
      int off = swz(r, lc*16);
      *(uint4*)(sAh + off) = *(const uint4*)(Agh + (size_t)r*HD + k0 + lc*8);
      *(uint4*)(sAl + off) = *(const uint4*)(Agl + (size_t)r*HD + k0 + lc*8);
      *(uint4*)(sBh + off) = *(const uint4*)(Bgh + (size_t)r*HD + k0 + lc*8);
      *(uint4*)(sBl + off) = *(const uint4*)(Bgl + (size_t)r*HD + k0 + lc*8);
    }
    __syncthreads();
    #pragma unroll
    for (int kk = 0; kk < 4; kk++) {
      unsigned Ah[2][4], Al[2][4], Bh[4][2], Bl[4][2];
      #pragma unroll
      for (int mt = 0; mt < 2; mt++) {
        int r = wm + mt*16 + (lane & 15);
        int cb = kk*32 + ((lane >> 4) << 4);
        int off = swz(r, cb);
        ldsm4(Ah[mt][0],Ah[mt][1],Ah[mt][2],Ah[mt][3], su32(sAh + off));
        ldsm4(Al[mt][0],Al[mt][1],Al[mt][2],Al[mt][3], su32(sAl + off));
      }
      #pragma unroll
      for (int p = 0; p < 2; p++) {
        int r = wn + p*16 + (lane & 15);
        int cb = kk*32 + ((lane >> 4) << 4);
        int off = swz(r, cb);
        unsigned r0,r1,r2,r3;
        ldsm4(r0,r1,r2,r3, su32(sBh + off));
        Bh[p*2][0]=r0; Bh[p*2][1]=r2; Bh[p*2+1][0]=r1; Bh[p*2+1][1]=r3;
        ldsm4(r0,r1,r2,r3, su32(sBl + off));
        Bl[p*2][0]=r0; Bl[p*2][1]=r2; Bl[p*2+1][0]=r1; Bl[p*2+1][1]=r3;
      }
      #pragma unroll
      for (int mt = 0; mt < 2; mt++)
        #pragma unroll
        for (int ns = 0; ns < 4; ns++) {
          mma16816(acc[mt][ns], Ah[mt], Bh[ns][0], Bh[ns][1]);
          mma16816(acc[mt][ns], Ah[mt], Bl[ns][0], Bl[ns][1]);
          mma16816(acc[mt][ns], Al[mt], Bh[ns][0], Bh[ns][1]);
        }
    }
    __syncthreads();
  }
  float* Sb = S + (size_t)z*CP*TP;
  #pragma unroll
  for (int mt = 0; mt < 2; mt++)
    #pragma unroll
    for (int ns = 0; ns < 4; ns++) {
      int row = wm + mt*16 + (lane >> 2);
      int col = t0 + wn + ns*8 + (lane & 3)*2;
      Sb[(size_t)row*TP + col]          = acc[mt][ns][0];
      Sb[(size_t)row*TP + col + 1]      = acc[mt][ns][1];
      Sb[(size_t)(row+8)*TP + col]      = acc[mt][ns][2];
      Sb[(size_t)(row+8)*TP + col + 1]  = acc[mt][ns][3];
    }
}

__global__ void __launch_bounds__(256) softmax_kernel(
  const float* __restrict__ S, bf16* __restrict__ Sh, bf16* __restrict__ Sl)
{
  int row = blockIdx.x;
  int z = row / CC, c = row % CC;
  const float* s = S + ((size_t)z*CP + c)*TP;
  float vals[4];
  float mx = -1e30f;
  #pragma unroll
  for (int ii = 0; ii < 4; ii++) {
    int j = threadIdx.x + ii*256;
    vals[ii] = (j < TTOT) ? s[j] : -1e30f;
    mx = fmaxf(mx, vals[ii]);
  }
  mx = blk_reduce(mx, true);
  float sum = 0.f;
  #pragma unroll
  for (int ii = 0; ii < 4; ii++) {
    int j = threadIdx.x + ii*256;
    if (j < TTOT) { vals[ii] = expf(vals[ii] - mx); sum += vals[ii]; }
  }
  sum = blk_reduce(sum, false);
  float inv = 1.f / sum;
  size_t base = ((size_t)z*CP + c)*TP;
  #pragma unroll
  for (int ii = 0; ii < 4; ii++) {
    int j = threadIdx.x + ii*256;
    if (j < TTOT) {
      float p = vals[ii] * inv;
      unsigned short h, l;
      split1(p, h, l);
      Sh[base + j] = __ushort_as_bfloat16(h);
      Sl[base + j] = __ushort_as_bfloat16(l);
    }
  }
}

__global__ void __launch_bounds__(128) attn_av(
  const bf16* __restrict__ sh_, const bf16* __restrict__ sl_,
  const bf16* __restrict__ vh, const bf16* __restrict__ vl,
  bf16* __restrict__ Oh, bf16* __restrict__ Ol)
{
  __shared__ char sm[32768];
  char* sAh = sm; char* sAl = sm + 8192; char* sBh = sm + 16384; char* sBl = sm + 24576;
  int z = blockIdx.z, b = z >> 3, n = z & 7;
  int d0 = blockIdx.x * 64;
  int tid = threadIdx.x, lane = tid & 31, warp = tid >> 5;
  int wm = (warp >> 1) * 32, wn = (warp & 1) * 32;
  const bf16* Agh = sh_ + (size_t)z*CP*TP;
  const bf16* Agl = sl_ + (size_t)z*CP*TP;
  const bf16* Bgh = vh + (size_t)b*TP*HD + d0;
  const bf16* Bgl = vl + (size_t)b*TP*HD + d0;

  float acc[2][4][4];
  #pragma unroll
  for (int i=0;i<2;i++)
    #pragma unroll
    for (int j=0;j<4;j++)
      #pragma unroll
      for (int e=0;e<4;e++) acc[i][j][e]=0.f;

  int lr = tid >> 3, lc = tid & 7;
  for (int k0 = 0; k0 < TP; k0 += 64) {
    #pragma unroll
    for (int rr = 0; rr < 4; rr++) {
      int r = lr + rr*16;
      int off = swz(r, lc*16);
      *(uint4*)(sAh + off) = *(const uint4*)(Agh + (size_t)r*TP + k0 + lc*8);
      *(uint4*)(sAl + off) = *(const uint4*)(Agl + (size_t)r*TP + k0 + lc*8);
      *(uint4*)(sBh + off) = *(const uint4*)(Bgh + (size_t)(k0 + r)*HD + lc*8);
      *(uint4*)(sBl + off) = *(const uint4*)(Bgl + (size_t)(k0 + r)*HD + lc*8);
    }
    __syncthreads();
    #pragma unroll
    for (int kk = 0; kk < 4; kk++) {
      unsigned Ah[2][4], Al[2][4], Bh[4][2], Bl[4][2];
      #pragma unroll
      for (int mt = 0; mt < 2; mt++) {
        int r = wm + mt*16 + (lane & 15);
        int cb = kk*32 + ((lane >> 4) << 4);
        int off = swz(r, cb);
        ldsm4(Ah[mt][0],Ah[mt][1],Ah[mt][2],Ah[mt][3], su32(sAh + off));
        ldsm4(Al[mt][0],Al[mt][1],Al[mt][2],Al[mt][3], su32(sAl + off));
      }
      #pragma unroll
      for (int p = 0; p < 2; p++) {
        int r = kk*16 + (lane & 15);
        int cb = (wn + p*16)*2 + ((lane >> 4) << 4);
        int off = swz(r, cb);
        unsigned r0,r1,r2,r3;
        ldsm4t(r0,r1,r2,r3, su32(sBh + off));
        Bh[p*2][0]=r0; Bh[p*2][1]=r1; Bh[p*2+1][0]=r2; Bh[p*2+1][1]=r3;
        ldsm4t(r0,r1,r2,r3, su32(sBl + off));
        Bl[p*2][0]=r0; Bl[p*2][1]=r1; Bl[p*2+1][0]=r2; Bl[p*2+1][1]=r3;
      }
      #pragma unroll
      for (int mt = 0; mt < 2; mt++)
        #pragma unroll
        for (int ns = 0; ns < 4; ns++) {
          mma16816(acc[mt][ns], Ah[mt], Bh[ns][0], Bh[ns][1]);
          mma16816(acc[mt][ns], Ah[mt], Bl[ns][0], Bl[ns][1]);
          mma16816(acc[mt][ns], Al[mt], Bh[ns][0], Bh[ns][1]);
        }
    }
    __syncthreads();
  }
  #pragma unroll
  for (int mt = 0; mt < 2; mt++)
    #pragma unroll
    for (int ns = 0; ns < 4; ns++) {
      int c = wm + mt*16 + (lane >> 2);
      int d = d0 + wn + ns*8 + (lane & 3)*2;
      #pragma unroll
      for (int e = 0; e < 4; e++) {
        int cc = c + ((e >= 2) ? 8 : 0);
        int dd = d + (e & 1);
        if (cc < CC) {
          unsigned short h, l;
          split1(acc[mt][ns][e], h, l);
          size_t idx = ((size_t)(b*CC + cc))*(NHH*HD) + n*HD + dd;
          Oh[idx] = __ushort_as_bfloat16(h);
          Ol[idx] = __ushort_as_bfloat16(l);
        }
      }
    }
}

// ---------------- elementwise ----------------
__global__ void qconv_kernel(const float* __restrict__ q, const int* __restrict__ pos,
                             bf16* __restrict__ qh, bf16* __restrict__ ql)
{
  int idx = blockIdx.x * blockDim.x + threadIdx.x;
  if (idx >= MTOT*NHH*128) return;
  int i = idx & 127;
  int mn = idx >> 7;
  int n = mn & 7, m = mn >> 3;
  int b = m / CC, c = m % CC;
  const float* p = q + (size_t)m*(NHH*HD) + n*HD;
  float x1 = p[i], x2 = p[i + 128];
  float ang = (float)pos[c] * expf(-(float)i * (9.210340371976184f/128.f));
  float sn, cs; sincosf(ang, &sn, &cs);
  float o1 = (x1*cs - x2*sn) * 0.0625f;
  float o2 = (x2*cs + x1*sn) * 0.0625f;
  size_t dst = ((size_t)(b*NHH + n)*CP + c)*HD;
  unsigned short h, l;
  split1(o1, h, l); qh[dst+i] = __ushort_as_bfloat16(h); ql[dst+i] = __ushort_as_bfloat16(l);
  split1(o2, h, l); qh[dst+i+128] = __ushort_as_bfloat16(h); ql[dst+i+128] = __ushort_as_bfloat16(l);
}

__global__ void kconv_kernel(const float* __restrict__ pk, const float* __restrict__ knew,
                             const int* __restrict__ pos,
                             bf16* __restrict__ kh, bf16* __restrict__ kl, int layer)
{
  int idx = blockIdx.x * blockDim.x + threadIdx.x;
  if (idx >= BB*TTOT*HD) return;
  int d = idx & 255;
  int bt = idx >> 8;
  int t = bt % TTOT, b = bt / TTOT;
  size_t dst = ((size_t)b*TP + t)*HD;
  unsigned short h, l;
  if (t < PP) {
    float x = pk[(((size_t)layer*BB + b)*PP + t)*HD + d];
    split1(x, h, l);
    kh[dst+d] = __ushort_as_bfloat16(h); kl[dst+d] = __ushort_as_bfloat16(l);
  } else if (d < 128) {
    int c = t - PP;
    const float* p = knew + (size_t)(b*CC + c)*HD;
    float x1 = p[d], x2 = p[d + 128];
    float ang = (float)pos[c] * expf(-(float)d * (9.210340371976184f/128.f));
    float sn, cs; sincosf(ang, &sn, &cs);
    float o1 = x1*cs - x2*sn;
    float o2 = x2*cs + x1*sn;
    split1(o1, h, l); kh[dst+d] = __ushort_as_bfloat16(h); kl[dst+d] = __ushort_as_bfloat16(l);
    split1(o2, h, l); kh[dst+d+128] = __ushort_as_bfloat16(h); kl[dst+d+128] = __ushort_as_bfloat16(l);
  }
}

__global__ void vconv_kernel(const float* __restrict__ pv, const float* __restrict__ vnew,
                             bf16* __restrict__ vh, bf16* __restrict__ vl, int layer)
{
  int idx = blockIdx.x * blockDim.x + threadIdx.x;
  if (idx >= BB*TTOT*HD) return;
  int d = idx & 255;
  int bt = idx >> 8;
  int t = bt % TTOT, b = bt / TTOT;
  float x = (t < PP) ? pv[(((size_t)layer*BB + b)*PP + t)*HD + d]
                     : vnew[(size_t)(b*CC + (t - PP))*HD + d];
  unsigned short h, l;
  split1(x, h, l);
  size_t dst = ((size_t)b*TP + t)*HD;
  vh[dst+d] = __ushort_as_bfloat16(h);
  vl[dst+d] = __ushort_as_bfloat16(l);
}

__global__ void __launch_bounds__(256) rmsnorm_bf(
  const float* __restrict__ x, const float* __restrict__ w,
  bf16* __restrict__ oh, bf16* __restrict__ ol)
{
  int row = blockIdx.x;
  const float* xr = x + (size_t)row*HH;
  float ss = 0.f;
  for (int j = threadIdx.x; j < HH; j += 256) { float v = xr[j]; ss += v*v; }
  ss = blk_reduce(ss, false);
  float sc = rsqrtf(ss * (1.f/HH) + 1e-6f);
  for (int j = threadIdx.x; j < HH; j += 256) {
    float v = xr[j] * sc * w[j];
    unsigned short h, l;
    split1(v, h, l);
    oh[(size_t)row*HH + j] = __ushort_as_bfloat16(h);
    ol[(size_t)row*HH + j] = __ushort_as_bfloat16(l);
  }
}

__global__ void timeemb_bf(const float* __restrict__ ts, bf16* __restrict__ xth, bf16* __restrict__ xtl)
{
  int idx = blockIdx.x * blockDim.x + threadIdx.x;
  if (idx >= MTOT*HH) return;
  int m = idx >> 10, j = idx & 1023;
  int b = m / CC;
  float t = ts[b];
  int i = (j < 512) ? j : (j - 512);
  float period = 4e-3f * expf((float)i * (6.907755278982137f/512.f));
  float ang = 6.283185307179586f * t / period;
  float v = (j < 512) ? sinf(ang) : cosf(ang);
  unsigned short h, l;
  split1(v, h, l);
  size_t dst = (size_t)m*(2*HH) + HH + j;
  xth[dst] = __ushort_as_bfloat16(h);
  xtl[dst] = __ushort_as_bfloat16(l);
}

__global__ void gelumul_bf(const float* __restrict__ gate, const float* __restrict__ up,
                           bf16* __restrict__ mh, bf16* __restrict__ ml)
{
  int idx = blockIdx.x * blockDim.x + threadIdx.x;
  if (idx >= MTOT*MLPD) return;
  float g = gate[idx];
  float t = tanhf(0.7978845608028654f * (g + 0.044715f*g*g*g));
  float v = 0.5f * g * (1.f + t) * up[idx];
  unsigned short h, l;
  split1(v, h, l);
  mh[idx] = __ushort_as_bfloat16(h);
  ml[idx] = __ushort_as_bfloat16(l);
}

// ---------------- orchestration ----------------
extern "C" void kernel_launch(void* const* d_in, const int* in_sizes, int n_in,
                              void* d_out, int out_size)
{
  const float* noisy   = (const float*)d_in[0];
  const float* tstep   = (const float*)d_in[1];
  const int*   pos_ids = (const int*)d_in[2];
  const float* pk      = (const float*)d_in[3];
  const float* pv      = (const float*)d_in[4];
  const float* in_w    = (const float*)d_in[5];
  const float* in_b    = (const float*)d_in[6];
  const float* t_in_w  = (const float*)d_in[7];
  const float* t_in_b  = (const float*)d_in[8];
  const float* t_out_w = (const float*)d_in[9];
  const float* t_out_b = (const float*)d_in[10];
  const float* out_w   = (const float*)d_in[11];
  const float* out_b   = (const float*)d_in[12];
  const float* fn_w    = (const float*)d_in[13];
  const float* ln1_w   = (const float*)d_in[14];
  const float* q_w     = (const float*)d_in[15];
  const float* k_w     = (const float*)d_in[16];
  const float* v_w     = (const float*)d_in[17];
  const float* o_w     = (const float*)d_in[18];
  const float* ln2_w   = (const float*)d_in[19];
  const float* gate_w  = (const float*)d_in[20];
  const float* up_w    = (const float*)d_in[21];
  const float* down_w  = (const float*)d_in[22];
  float* out = (float*)d_out;

  float *x,*q,*k,*v,*s,*gate,*up;
  bf16 *hh,*hl,*xth,*xtl,*midh,*midl,*aoh,*aol,*nh,*nl;
  bf16 *qh,*ql,*kh,*kl,*vh,*vl,*sh,*sl;
  bf16 *qwh,*qwl,*kwh,*kwl,*vwh,*vwl,*owh,*owl,*gwh,*gwl,*uwh,*uwl,*dwh,*dwl;
  bf16 *tinh,*tinl,*touth,*toutl,*outwh,*outwl,*inwh,*inwl;

  cudaGetSymbolAddress((void**)&x, g_x);
  cudaGetSymbolAddress((void**)&q, g_q);
  cudaGetSymbolAddress((void**)&k, g_k);
  cudaGetSymbolAddress((void**)&v, g_v);
  cudaGetSymbolAddress((void**)&s, g_s);
  cudaGetSymbolAddress((void**)&gate, g_gate);
  cudaGetSymbolAddress((void**)&up, g_up);
  cudaGetSymbolAddress((void**)&hh, g_hh);   cudaGetSymbolAddress((void**)&hl, g_hl);
  cudaGetSymbolAddress((void**)&xth, g_xth); cudaGetSymbolAddress((void**)&xtl, g_xtl);
  cudaGetSymbolAddress((void**)&midh, g_midh); cudaGetSymbolAddress((void**)&midl, g_midl);
  cudaGetSymbolAddress((void**)&aoh, g_aoh); cudaGetSymbolAddress((void**)&aol, g_aol);
  cudaGetSymbolAddress((void**)&nh, g_nh);   cudaGetSymbolAddress((void**)&nl, g_nl);
  cudaGetSymbolAddress((void**)&qh, g_qh);   cudaGetSymbolAddress((void**)&ql, g_ql);
  cudaGetSymbolAddress((void**)&kh, g_kh);   cudaGetSymbolAddress((void**)&kl, g_kl);
  cudaGetSymbolAddress((void**)&vh, g_vh);   cudaGetSymbolAddress((void**)&vl, g_vl);
  cudaGetSymbolAddress((void**)&sh, g_sh);   cudaGetSymbolAddress((void**)&sl, g_sl);
  cudaGetSymbolAddress((void**)&qwh, g_qwh); cudaGetSymbolAddress((void**)&qwl, g_qwl);
  cudaGetSymbolAddress((void**)&kwh, g_kwh); cudaGetSymbolAddress((void**)&kwl, g_kwl);
  cudaGetSymbolAddress((void**)&vwh, g_vwh); cudaGetSymbolAddress((void**)&vwl, g_vwl);
  cudaGetSymbolAddress((void**)&owh, g_owh); cudaGetSymbolAddress((void**)&owl, g_owl);
  cudaGetSymbolAddress((void**)&gwh, g_gwh); cudaGetSymbolAddress((void**)&gwl, g_gwl);
  cudaGetSymbolAddress((void**)&uwh, g_uwh); cudaGetSymbolAddress((void**)&uwl, g_uwl);
  cudaGetSymbolAddress((void**)&dwh, g_dwh); cudaGetSymbolAddress((void**)&dwl, g_dwl);
  cudaGetSymbolAddress((void**)&tinh, g_tinh);   cudaGetSymbolAddress((void**)&tinl, g_tinl);
  cudaGetSymbolAddress((void**)&touth, g_touth); cudaGetSymbolAddress((void**)&toutl, g_toutl);
  cudaGetSymbolAddress((void**)&outwh, g_outwh); cudaGetSymbolAddress((void**)&outwl, g_outwl);
  cudaGetSymbolAddress((void**)&inwh, g_inwh);   cudaGetSymbolAddress((void**)&inwl, g_inwl);

  cudaFuncSetAttribute(gemm_bf<1>,  cudaFuncAttributeMaxDynamicSharedMemorySize, SMEM_GEMM);
  cudaFuncSetAttribute(gemm_bf<9>,  cudaFuncAttributeMaxDynamicSharedMemorySize, SMEM_GEMM);
  cudaFuncSetAttribute(gemm_bf<13>, cudaFuncAttributeMaxDynamicSharedMemorySize, SMEM_GEMM);
  cudaFuncSetAttribute(gemm_bf<18>, cudaFuncAttributeMaxDynamicSharedMemorySize, SMEM_GEMM);
  cudaFuncSetAttribute(qkv_gemm,    cudaFuncAttributeMaxDynamicSharedMemorySize, SMEM_GEMM);
  cudaFuncSetAttribute(gateup_gemm, cudaFuncAttributeMaxDynamicSharedMemorySize, SMEM_GEMM);

  // ---- weight conversion (once per call) ----
  {
    int n;
    n = LNUM*2048*1024/4; convsplit<<<(n+255)/256,256>>>(q_w, qwh, qwl, n);
    n = LNUM*256*1024/4;  convsplit<<<(n+255)/256,256>>>(k_w, kwh, kwl, n);
    n = LNUM*256*1024/4;  convsplit<<<(n+255)/256,256>>>(v_w, vwh, vwl, n);
    n = LNUM*1024*2048/4; convsplit<<<(n+255)/256,256>>>(o_w, owh, owl, n);
    n = LNUM*4096*1024/4; convsplit<<<(n+255)/256,256>>>(gate_w, gwh, gwl, n);
    n = LNUM*4096*1024/4; convsplit<<<(n+255)/256,256>>>(up_w, uwh, uwl, n);
    n = LNUM*1024*4096/4; convsplit<<<(n+255)/256,256>>>(down_w, dwh, dwl, n);
    n = 1024*2048/4;      convsplit<<<(n+255)/256,256>>>(t_in_w, tinh, tinl, n);
    n = 1024*1024/4;      convsplit<<<(n+255)/256,256>>>(t_out_w, touth, toutl, n);
    n = 32*1024/4;        convsplit<<<(n+255)/256,256>>>(out_w, outwh, outwl, n);
    padconv32<<<(1024*32+255)/256,256>>>(in_w, inwh, inwl, 1024);
    padconv32<<<(MTOT*32+255)/256,256>>>(noisy, nh, nl, MTOT);
  }

  // ---- prologue ----
  gemm_bf<9><<<dim3(16,4,1),256,SMEM_GEMM>>>(nh, nl, inwh, inwl, in_b, nullptr, xth, xtl,
                                             MTOT, 1024, 64, 64, 64, 2048);
  timeemb_bf<<<(MTOT*HH+255)/256,256>>>(tstep, xth, xtl);
  gemm_bf<13><<<dim3(16,4,1),256,SMEM_GEMM>>>(xth, xtl, tinh, tinl, t_in_b, nullptr, hh, hl,
                                              MTOT, 1024, 2048, 2048, 2048, 1024);
  gemm_bf<1><<<dim3(16,4,1),256,SMEM_GEMM>>>(hh, hl, touth, toutl, t_out_b, x, nullptr, nullptr,
                                             MTOT, 1024, 1024, 1024, 1024, 1024);

  for (int l = 0; l < LNUM; l++) {
    rmsnorm_bf<<<MTOT,256>>>(x, ln1_w + l*HH, hh, hl);
    qkv_gemm<<<dim3(40,4,1),256,SMEM_GEMM>>>(hh, hl, qwh, qwl, kwh, kwl, vwh, vwl, q, k, v, l);
    qconv_kernel<<<(MTOT*NHH*128+255)/256,256>>>(q, pos_ids, qh, ql);
    kconv_kernel<<<(BB*TTOT*HD+255)/256,256>>>(pk, k, pos_ids, kh, kl, l);
    vconv_kernel<<<(BB*TTOT*HD+255)/256,256>>>(pv, v, vh, vl, l);
    attn_scores<<<dim3(TP/64,1,BB*NHH),128>>>(qh, ql, kh, kl, s);
    softmax_kernel<<<BB*NHH*CC,256>>>(s, sh, sl);
    attn_av<<<dim3(HD/64,1,BB*NHH),128>>>(sh, sl, vh, vl, aoh, aol);
    // O-proj: residual atomic, split-K x2 (K=2048 -> 2x1024)
    gemm_bf<18><<<dim3(16,4,2),256,SMEM_GEMM>>>(aoh, aol,
        owh + (size_t)l*1024*2048, owl + (size_t)l*1024*2048,
        nullptr, x, nullptr, nullptr, MTOT, 1024, 1024, 2048, 2048, 1024);
    rmsnorm_bf<<<MTOT,256>>>(x, ln2_w + l*HH, hh, hl);
    gateup_gemm<<<dim3(64,4,2),256,SMEM_GEMM>>>(hh, hl, gwh, gwl, uwh, uwl, gate, up, l);
    gelumul_bf<<<(MTOT*MLPD+255)/256,256>>>(gate, up, midh, midl);
    // down: residual atomic, split-K x2 (K=4096 -> 2x2048)
    gemm_bf<18><<<dim3(16,4,2),256,SMEM_GEMM>>>(midh, midl,
        dwh + (size_t)l*1024*4096, dwl + (size_t)l*1024*4096,
        nullptr, x, nullptr, nullptr, MTOT, 1024, 2048, 4096, 4096, 1024);
  }

  rmsnorm_bf<<<MTOT,256>>>(x, fn_w, hh, hl);
  gemm_bf<1><<<dim3(1,4,1),256,SMEM_GEMM>>>(hh, hl, outwh, outwl, out_b, out, nullptr, nullptr,
                                            MTOT, 32, 1024, 1024, 1024, 32);
}

// round 8
// speedup vs baseline: 4.5824x; 1.7196x over previous
#include <cuda_runtime.h>
#include <cuda_bf16.h>
#include <cstdint>

#define LNUM 18
#define BB 8
#define CC 50
#define AA 32
#define HH 1024
#define NHH 8
#define HD 256
#define PP 800
#define MLPD 4096
#define MTOT 400
#define TTOT 850
#define TP 896
#define CP 64
#define MPAD 512
#define SMEM_GEMM (96*1024)

typedef __nv_bfloat16 bf16;

// ---------------- fp32 scratch ----------------
__device__ __align__(256) float g_x[MTOT*HH];
__device__ __align__(256) float g_q[MTOT*NHH*HD];
__device__ __align__(256) float g_k[MTOT*HD];
__device__ __align__(256) float g_v[MTOT*HD];
__device__ __align__(256) float g_s[BB*NHH*CP*TP];
__device__ __align__(256) float g_gate[MTOT*MLPD];
__device__ __align__(256) float g_up[MTOT*MLPD];

// ---------------- bf16 activations (hi/lo), padded to MPAD rows ----------------
__device__ __align__(256) bf16 g_hh[MPAD*HH];
__device__ __align__(256) bf16 g_hl[MPAD*HH];
__device__ __align__(256) bf16 g_xth[MPAD*2*HH];
__device__ __align__(256) bf16 g_xtl[MPAD*2*HH];
__device__ __align__(256) bf16 g_midh[MPAD*MLPD];
__device__ __align__(256) bf16 g_midl[MPAD*MLPD];
__device__ __align__(256) bf16 g_aoh[MPAD*NHH*HD];
__device__ __align__(256) bf16 g_aol[MPAD*NHH*HD];
__device__ __align__(256) bf16 g_nh[MPAD*64];
__device__ __align__(256) bf16 g_nl[MPAD*64];

// ---------------- bf16 attention operands ----------------
__device__ __align__(256) bf16 g_qh[BB*NHH*CP*HD];
__device__ __align__(256) bf16 g_ql[BB*NHH*CP*HD];
__device__ __align__(256) bf16 g_kh[BB*TP*HD];
__device__ __align__(256) bf16 g_kl[BB*TP*HD];
__device__ __align__(256) bf16 g_vh[BB*TP*HD];
__device__ __align__(256) bf16 g_vl[BB*TP*HD];
__device__ __align__(256) bf16 g_sh[BB*NHH*CP*TP];
__device__ __align__(256) bf16 g_sl[BB*NHH*CP*TP];

// ---------------- bf16 weights (hi/lo) ----------------
__device__ bf16 g_qwh[LNUM*2048*1024];
__device__ bf16 g_qwl[LNUM*2048*1024];
__device__ bf16 g_kwh[LNUM*256*1024];
__device__ bf16 g_kwl[LNUM*256*1024];
__device__ bf16 g_vwh[LNUM*256*1024];
__device__ bf16 g_vwl[LNUM*256*1024];
__device__ bf16 g_owh[LNUM*1024*2048];
__device__ bf16 g_owl[LNUM*1024*2048];
__device__ bf16 g_gwh[LNUM*4096*1024];
__device__ bf16 g_gwl[LNUM*4096*1024];
__device__ bf16 g_uwh[LNUM*4096*1024];
__device__ bf16 g_uwl[LNUM*4096*1024];
__device__ bf16 g_dwh[LNUM*1024*4096];
__device__ bf16 g_dwl[LNUM*1024*4096];
__device__ bf16 g_tinh[1024*2048];
__device__ bf16 g_tinl[1024*2048];
__device__ bf16 g_touth[1024*1024];
__device__ bf16 g_toutl[1024*1024];
__device__ bf16 g_outwh[64*1024];
__device__ bf16 g_outwl[64*1024];
__device__ bf16 g_inwh[1024*64];
__device__ bf16 g_inwl[1024*64];

// ---------------- helpers ----------------
__device__ __forceinline__ unsigned su32(const void* p){ return (unsigned)__cvta_generic_to_shared(p); }
__device__ __forceinline__ int swz(int r, int cb){ return r*128 + (cb ^ ((r&7)<<4)); }

__device__ __forceinline__ void ldsm4(unsigned& a,unsigned& b,unsigned& c,unsigned& d, unsigned addr){
  asm volatile("ldmatrix.sync.aligned.m8n8.x4.shared.b16 {%0,%1,%2,%3},[%4];"
    :"=r"(a),"=r"(b),"=r"(c),"=r"(d):"r"(addr));
}
__device__ __forceinline__ void ldsm4t(unsigned& a,unsigned& b,unsigned& c,unsigned& d, unsigned addr){
  asm volatile("ldmatrix.sync.aligned.m8n8.x4.trans.shared.b16 {%0,%1,%2,%3},[%4];"
    :"=r"(a),"=r"(b),"=r"(c),"=r"(d):"r"(addr));
}
__device__ __forceinline__ void mma16816(float* c, const unsigned* a, unsigned b0, unsigned b1){
  asm volatile("mma.sync.aligned.m16n8k16.row.col.f32.bf16.bf16.f32 {%0,%1,%2,%3},{%4,%5,%6,%7},{%8,%9},{%0,%1,%2,%3};"
    :"+f"(c[0]),"+f"(c[1]),"+f"(c[2]),"+f"(c[3])
    :"r"(a[0]),"r"(a[1]),"r"(a[2]),"r"(a[3]),"r"(b0),"r"(b1));
}
__device__ __forceinline__ void split1(float x, unsigned short& h, unsigned short& l){
  __nv_bfloat16 bh = __float2bfloat16_rn(x);
  h = __bfloat16_as_ushort(bh);
  l = __bfloat16_as_ushort(__float2bfloat16_rn(x - __bfloat162float(bh)));
}
__device__ __forceinline__ void cpa16(void* sdst, const void* gsrc){
  unsigned d = su32(sdst);
  asm volatile("cp.async.cg.shared.global [%0],[%1],16;" :: "r"(d),"l"(gsrc));
}

__device__ __forceinline__ float blk_reduce(float v, bool ismax) {
    __shared__ float sh[8];
    int lane = threadIdx.x & 31, wid = threadIdx.x >> 5;
    #pragma unroll
    for (int o = 16; o > 0; o >>= 1) {
        float w = __shfl_xor_sync(0xffffffffu, v, o);
        v = ismax ? fmaxf(v, w) : (v + w);
    }
    if (lane == 0) sh[wid] = v;
    __syncthreads();
    if (threadIdx.x == 0) {
        float r = sh[0];
        int nw = (blockDim.x + 31) >> 5;
        for (int i = 1; i < nw; i++) r = ismax ? fmaxf(r, sh[i]) : (r + sh[i]);
        sh[0] = r;
    }
    __syncthreads();
    float r = sh[0];
    __syncthreads();
    return r;
}

// ---------------- GEMM stage loader (48KB: Ah16K,Al16K,Bh8K,Bl8K) ----------------
__device__ __forceinline__ void load_stage(char* st,
  const bf16* Ah, const bf16* Al, const bf16* Bh, const bf16* Bl,
  int lda, int ldb, int k0, int tid)
{
  char* sAh = st; char* sAl = st+16384; char* sBh = st+32768; char* sBl = st+40960;
  int r0 = tid>>3, ch = tid&7;
  #pragma unroll
  for(int e=0;e<4;e++){
    int r = r0 + e*32;
    int off = swz(r, ch*16);
    cpa16(sAh+off, Ah + (size_t)r*lda + k0 + ch*8);
    cpa16(sAl+off, Al + (size_t)r*lda + k0 + ch*8);
  }
  #pragma unroll
  for(int e=0;e<2;e++){
    int r = r0 + e*32;
    int off = swz(r, ch*16);
    cpa16(sBh+off, Bh + (size_t)r*ldb + k0 + ch*8);
    cpa16(sBl+off, Bl + (size_t)r*ldb + k0 + ch*8);
  }
}

__device__ __forceinline__ void compute_stage(char* st, float acc[2][4][4], int lane, int wm, int wn)
{
  char* sAh = st; char* sAl = st+16384; char* sBh = st+32768; char* sBl = st+40960;
  #pragma unroll
  for(int kk=0;kk<4;kk++){
    unsigned Ah[2][4], Al[2][4], Bh[4][2], Bl[4][2];
    #pragma unroll
    for(int mt=0;mt<2;mt++){
      int r = wm + mt*16 + (lane & 15);
      int cb = kk*32 + ((lane >> 4) << 4);
      int off = swz(r, cb);
      ldsm4(Ah[mt][0],Ah[mt][1],Ah[mt][2],Ah[mt][3], su32(sAh + off));
      ldsm4(Al[mt][0],Al[mt][1],Al[mt][2],Al[mt][3], su32(sAl + off));
    }
    #pragma unroll
    for(int p=0;p<2;p++){
      int r = wn + p*16 + (lane & 15);
      int cb = kk*32 + ((lane >> 4) << 4);
      int off = swz(r, cb);
      unsigned r0,r1,r2,r3;
      ldsm4(r0,r1,r2,r3, su32(sBh + off));
      Bh[p*2][0]=r0; Bh[p*2][1]=r2; Bh[p*2+1][0]=r1; Bh[p*2+1][1]=r3;
      ldsm4(r0,r1,r2,r3, su32(sBl + off));
      Bl[p*2][0]=r0; Bl[p*2][1]=r2; Bl[p*2+1][0]=r1; Bl[p*2+1][1]=r3;
    }
    #pragma unroll
    for(int mt=0;mt<2;mt++)
      #pragma unroll
      for(int ns=0;ns<4;ns++){
        mma16816(acc[mt][ns], Ah[mt], Bh[ns][0], Bh[ns][1]);
        mma16816(acc[mt][ns], Ah[mt], Bl[ns][0], Bl[ns][1]);
        mma16816(acc[mt][ns], Al[mt], Bh[ns][0], Bh[ns][1]);
      }
  }
}

// EPI bits: 1=bias (z==0 slice only), 2=residual fp32 read-add, 4=silu, 8=store bf16 hi/lo, 16=atomicAdd fp32
template<int EPI>
__global__ void __launch_bounds__(256,2) gemm_bf(
  const bf16* Ah, const bf16* Al, const bf16* Bh, const bf16* Bl,
  const float* bias, float* Cf, bf16* Ch, bf16* Cl,
  int M, int N, int K, int lda, int ldb, int ldc)
{
  extern __shared__ char rawsm[];
  char* st0 = rawsm; char* st1 = rawsm + 49152;
  int tid = threadIdx.x, lane = tid&31, warp = tid>>5;
  int wm = (warp>>1)*32, wn = (warp&1)*32;
  int m0 = blockIdx.y*128, n0 = blockIdx.x*64;
  size_t kofs = (size_t)blockIdx.z * K;
  const float* bz = (blockIdx.z == 0) ? bias : nullptr;

  float acc[2][4][4];
  #pragma unroll
  for(int i=0;i<2;i++)
    #pragma unroll
    for(int j=0;j<4;j++)
      #pragma unroll
      for(int e=0;e<4;e++) acc[i][j][e]=0.f;

  const bf16* Ahp = Ah + (size_t)m0*lda + kofs;
  const bf16* Alp = Al + (size_t)m0*lda + kofs;
  const bf16* Bhp = Bh + (size_t)n0*ldb + kofs;
  const bf16* Blp = Bl + (size_t)n0*ldb + kofs;
  int nk = K >> 6;
  load_stage(st0, Ahp, Alp, Bhp, Blp, lda, ldb, 0, tid);
  asm volatile("cp.async.commit_group;\n");
  for(int i=0;i<nk;i++){
    if(i+1 < nk){
      load_stage((i&1)?st0:st1, Ahp, Alp, Bhp, Blp, lda, ldb, (i+1)<<6, tid);
      asm volatile("cp.async.commit_group;\n");
      asm volatile("cp.async.wait_group 1;\n");
    } else {
      asm volatile("cp.async.wait_group 0;\n");
    }
    __syncthreads();
    compute_stage((i&1)?st1:st0, acc, lane, wm, wn);
    __syncthreads();
  }
  #pragma unroll
  for(int mt=0;mt<2;mt++)
    #pragma unroll
    for(int ns=0;ns<4;ns++){
      int row = m0 + wm + mt*16 + (lane>>2);
      int col = n0 + wn + ns*8 + (lane&3)*2;
      #pragma unroll
      for(int e=0;e<4;e++){
        int rr = row + ((e>=2)?8:0);
        int cc = col + (e&1);
        if(rr < M && cc < N){
          float v = acc[mt][ns][e];
          if((EPI&1) && bz) v += bz[cc];
          if(EPI&4) v = v/(1.f+expf(-v));
          if(EPI&16){
            atomicAdd(&Cf[(size_t)rr*ldc+cc], v);
          } else if(EPI&8){
            unsigned short h,l; split1(v,h,l);
            Ch[(size_t)rr*ldc+cc] = __ushort_as_bfloat16(h);
            Cl[(size_t)rr*ldc+cc] = __ushort_as_bfloat16(l);
          } else {
            if(EPI&2) v += Cf[(size_t)rr*ldc+cc];
            Cf[(size_t)rr*ldc+cc] = v;
          }
        }
      }
    }
}

// fused QKV with split-K (blockIdx.z in {0,1}, K slice 512), atomic stores into zeroed q/k/v
__global__ void __launch_bounds__(256,2) qkv_gemm(
  const bf16* Ah, const bf16* Al,
  const bf16* qwh, const bf16* qwl, const bf16* kwh, const bf16* kwl,
  const bf16* vwh, const bf16* vwl,
  float* q, float* k, float* v, int layer)
{
  extern __shared__ char rawsm[];
  char* st0 = rawsm; char* st1 = rawsm + 49152;
  int bx = blockIdx.x, m0 = blockIdx.y*128;
  size_t kofs = (size_t)blockIdx.z * 512;
  const bf16 *Bh, *Bl; float* C; int n0, ldc;
  if (bx < 32) {
    size_t w = (size_t)layer*2048*1024;
    Bh = qwh + w; Bl = qwl + w; C = q; n0 = bx*64; ldc = 2048;
  } else if (bx < 36) {
    size_t w = (size_t)layer*256*1024;
    Bh = kwh + w; Bl = kwl + w; C = k; n0 = (bx-32)*64; ldc = 256;
  } else {
    size_t w = (size_t)layer*256*1024;
    Bh = vwh + w; Bl = vwl + w; C = v; n0 = (bx-36)*64; ldc = 256;
  }
  int tid = threadIdx.x, lane = tid&31, warp = tid>>5;
  int wm = (warp>>1)*32, wn = (warp&1)*32;

  float acc[2][4][4];
  #pragma unroll
  for(int i=0;i<2;i++)
    #pragma unroll
    for(int j=0;j<4;j++)
      #pragma unroll
      for(int e=0;e<4;e++) acc[i][j][e]=0.f;

  const bf16* Ahp = Ah + (size_t)m0*1024 + kofs;
  const bf16* Alp = Al + (size_t)m0*1024 + kofs;
  const bf16* Bhp = Bh + (size_t)n0*1024 + kofs;
  const bf16* Blp = Bl + (size_t)n0*1024 + kofs;
  const int nk = 8;   // 512/64
  load_stage(st0, Ahp, Alp, Bhp, Blp, 1024, 1024, 0, tid);
  asm volatile("cp.async.commit_group;\n");
  for(int i=0;i<nk;i++){
    if(i+1 < nk){
      load_stage((i&1)?st0:st1, Ahp, Alp, Bhp, Blp, 1024, 1024, (i+1)<<6, tid);
      asm volatile("cp.async.commit_group;\n");
      asm volatile("cp.async.wait_group 1;\n");
    } else {
      asm volatile("cp.async.wait_group 0;\n");
    }
    __syncthreads();
    compute_stage((i&1)?st1:st0, acc, lane, wm, wn);
    __syncthreads();
  }
  #pragma unroll
  for(int mt=0;mt<2;mt++)
    #pragma unroll
    for(int ns=0;ns<4;ns++){
      int row = m0 + wm + mt*16 + (lane>>2);
      int col = n0 + wn + ns*8 + (lane&3)*2;
      #pragma unroll
      for(int e=0;e<4;e++){
        int rr = row + ((e>=2)?8:0);
        int cc = col + (e&1);
        if(rr < MTOT)
          atomicAdd(&C[(size_t)rr*ldc+cc], acc[mt][ns][e]);
      }
    }
}

// gate/up batched over blockIdx.z (no split-K; grid already 512)
__global__ void __launch_bounds__(256,2) gateup_gemm(
  const bf16* Ah, const bf16* Al,
  const bf16* gwh, const bf16* gwl, const bf16* uwh, const bf16* uwl,
  float* gate, float* up, int layer)
{
  extern __shared__ char rawsm[];
  char* st0 = rawsm; char* st1 = rawsm + 49152;
  size_t w = (size_t)layer*4096*1024;
  const bf16* Bh = blockIdx.z ? (uwh+w) : (gwh+w);
  const bf16* Bl = blockIdx.z ? (uwl+w) : (gwl+w);
  float* C = blockIdx.z ? up : gate;
  int tid = threadIdx.x, lane = tid&31, warp = tid>>5;
  int wm = (warp>>1)*32, wn = (warp&1)*32;
  int m0 = blockIdx.y*128, n0 = blockIdx.x*64;

  float acc[2][4][4];
  #pragma unroll
  for(int i=0;i<2;i++)
    #pragma unroll
    for(int j=0;j<4;j++)
      #pragma unroll
      for(int e=0;e<4;e++) acc[i][j][e]=0.f;

  const bf16* Ahp = Ah + (size_t)m0*1024;
  const bf16* Alp = Al + (size_t)m0*1024;
  const bf16* Bhp = Bh + (size_t)n0*1024;
  const bf16* Blp = Bl + (size_t)n0*1024;
  const int nk = 16;
  load_stage(st0, Ahp, Alp, Bhp, Blp, 1024, 1024, 0, tid);
  asm volatile("cp.async.commit_group;\n");
  for(int i=0;i<nk;i++){
    if(i+1 < nk){
      load_stage((i&1)?st0:st1, Ahp, Alp, Bhp, Blp, 1024, 1024, (i+1)<<6, tid);
      asm volatile("cp.async.commit_group;\n");
      asm volatile("cp.async.wait_group 1;\n");
    } else {
      asm volatile("cp.async.wait_group 0;\n");
    }
    __syncthreads();
    compute_stage((i&1)?st1:st0, acc, lane, wm, wn);
    __syncthreads();
  }
  #pragma unroll
  for(int mt=0;mt<2;mt++)
    #pragma unroll
    for(int ns=0;ns<4;ns++){
      int row = m0 + wm + mt*16 + (lane>>2);
      int col = n0 + wn + ns*8 + (lane&3)*2;
      #pragma unroll
      for(int e=0;e<4;e++){
        int rr = row + ((e>=2)?8:0);
        int cc = col + (e&1);
        if(rr < MTOT)
          C[(size_t)rr*4096+cc] = acc[mt][ns][e];
      }
    }
}

// ---------------- weight conversion ----------------
__global__ void convsplit(const float* __restrict__ s, bf16* __restrict__ h, bf16* __restrict__ l, int n4)
{
  int i = blockIdx.x*blockDim.x + threadIdx.x;
  if(i >= n4) return;
  float4 v = ((const float4*)s)[i];
  unsigned short h0,l0,h1,l1,h2,l2,h3,l3;
  split1(v.x,h0,l0); split1(v.y,h1,l1); split1(v.z,h2,l2); split1(v.w,h3,l3);
  ((uint2*)h)[i] = make_uint2((unsigned)h0|((unsigned)h1<<16), (unsigned)h2|((unsigned)h3<<16));
  ((uint2*)l)[i] = make_uint2((unsigned)l0|((unsigned)l1<<16), (unsigned)l2|((unsigned)l3<<16));
}

__global__ void padconv32(const float* __restrict__ s, bf16* __restrict__ h, bf16* __restrict__ l, int rows)
{
  int i = blockIdx.x*blockDim.x + threadIdx.x;
  if(i >= rows*32) return;
  int r = i >> 5, c = i & 31;
  unsigned short hh, ll;
  split1(s[i], hh, ll);
  h[r*64+c] = __ushort_as_bfloat16(hh);
  l[r*64+c] = __ushort_as_bfloat16(ll);
}

// ---------------- silu + bf16 split (for split-K t_in) ----------------
__global__ void silu_split(const float* __restrict__ in, bf16* __restrict__ oh, bf16* __restrict__ ol, int n)
{
  int i = blockIdx.x*blockDim.x + threadIdx.x;
  if (i >= n) return;
  float v = in[i];
  v = v/(1.f+expf(-v));
  unsigned short h, l;
  split1(v, h, l);
  oh[i] = __ushort_as_bfloat16(h);
  ol[i] = __ushort_as_bfloat16(l);
}

// ---------------- attention (mma.sync, proven) ----------------
__global__ void __launch_bounds__(128) attn_scores(
  const bf16* __restrict__ qh, const bf16* __restrict__ ql,
  const bf16* __restrict__ kh, const bf16* __restrict__ kl,
  float* __restrict__ S)
{
  __shared__ char sm[32768];
  char* sAh = sm; char* sAl = sm + 8192; char* sBh = sm + 16384; char* sBl = sm + 24576;
  int z = blockIdx.z, b = z >> 3;
  int t0 = blockIdx.x * 64;
  int tid = threadIdx.x, lane = tid & 31, warp = tid >> 5;
  int wm = (warp >> 1) * 32, wn = (warp & 1) * 32;
  const bf16* Agh = qh + (size_t)z*CP*HD;
  const bf16* Agl = ql + (size_t)z*CP*HD;
  const bf16* Bgh = kh + ((size_t)b*TP + t0)*HD;
  const bf16* Bgl = kl + ((size_t)b*TP + t0)*HD;

  float acc[2][4][4];
  #pragma unroll
  for (int i=0;i<2;i++)
    #pragma unroll
    for (int j=0;j<4;j++)
      #pragma unroll
      for (int e=0;e<4;e++) acc[i][j][e]=0.f;

  int lr = tid >> 3, lc = tid & 7;
  for (int k0 = 0; k0 < HD; k0 += 64) {
    #pragma unroll
    for (int rr = 0; rr < 4; rr++) {
      int r = lr + rr*16;
      int off = swz(r, lc*16);
      *(uint4*)(sAh + off) = *(const uint4*)(Agh + (size_t)r*HD + k0 + lc*8);
      *(uint4*)(sAl + off) = *(const uint4*)(Agl + (size_t)r*HD + k0 + lc*8);
      *(uint4*)(sBh + off) = *(const uint4*)(Bgh + (size_t)r*HD + k0 + lc*8);
      *(uint4*)(sBl + off) = *(const uint4*)(Bgl + (size_t)r*HD + k0 + lc*8);
    }
    __syncthreads();
    #pragma unroll
    for (int kk = 0; kk < 4; kk++) {
      unsigned Ah[2][4], Al[2][4], Bh[4][2], Bl[4][2];
      #pragma unroll
      for (int mt = 0; mt < 2; mt++) {
        int r = wm + mt*16 + (lane & 15);
        int cb = kk*32 + ((lane >> 4) << 4);
        int off = swz(r, cb);
        ldsm4(Ah[mt][0],Ah[mt][1],Ah[mt][2],Ah[mt][3], su32(sAh + off));
        ldsm4(Al[mt][0],Al[mt][1],Al[mt][2],Al[mt][3], su32(sAl + off));
      }
      #pragma unroll
      for (int p = 0; p < 2; p++) {
        int r = wn + p*16 + (lane & 15);
        int cb = kk*32 + ((lane >> 4) << 4);
        int off = swz(r, cb);
        unsigned r0,r1,r2,r3;
        ldsm4(r0,r1,r2,r3, su32(sBh + off));
        Bh[p*2][0]=r0; Bh[p*2][1]=r2; Bh[p*2+1][0]=r1; Bh[p*2+1][1]=r3;
        ldsm4(r0,r1,r2,r3, su32(sBl + off));
        Bl[p*2][0]=r0; Bl[p*2][1]=r2; Bl[p*2+1][0]=r1; Bl[p*2+1][1]=r3;
      }
      #pragma unroll
      for (int mt = 0; mt < 2; mt++)
        #pragma unroll
        for (int ns = 0; ns < 4; ns++) {
          mma16816(acc[mt][ns], Ah[mt], Bh[ns][0], Bh[ns][1]);
          mma16816(acc[mt][ns], Ah[mt], Bl[ns][0], Bl[ns][1]);
          mma16816(acc[mt][ns], Al[mt], Bh[ns][0], Bh[ns][1]);
        }
    }
    __syncthreads();
  }
  float* Sb = S + (size_t)z*CP*TP;
  #pragma unroll
  for (int mt = 0; mt < 2; mt++)
    #pragma unroll
    for (int ns = 0; ns < 4; ns++) {
      int row = wm + mt*16 + (lane >> 2);
      int col = t0 + wn + ns*8 + (lane & 3)*2;
      Sb[(size_t)row*TP + col]          = acc[mt][ns][0];
      Sb[(size_t)row*TP + col + 1]      = acc[mt][ns][1];
      Sb[(size_t)(row+8)*TP + col]      = acc[mt][ns][2];
      Sb[(size_t)(row+8)*TP + col + 1]  = acc[mt][ns][3];
    }
}

__global__ void __launch_bounds__(256) softmax_kernel(
  const float* __restrict__ S, bf16* __restrict__ Sh, bf16* __restrict__ Sl)
{
  int row = blockIdx.x;
  int z = row / CC, c = row % CC;
  const float* s = S + ((size_t)z*CP + c)*TP;
  float vals[4];
  float mx = -1e30f;
  #pragma unroll
  for (int ii = 0; ii < 4; ii++) {
    int j = threadIdx.x + ii*256;
    vals[ii] = (j < TTOT) ? s[j] : -1e30f;
    mx = fmaxf(mx, vals[ii]);
  }
  mx = blk_reduce(mx, true);
  float sum = 0.f;
  #pragma unroll
  for (int ii = 0; ii < 4; ii++) {
    int j = threadIdx.x + ii*256;
    if (j < TTOT) { vals[ii] = expf(vals[ii] - mx); sum += vals[ii]; }
  }
  sum = blk_reduce(sum, false);
  float inv = 1.f / sum;
  size_t base = ((size_t)z*CP + c)*TP;
  #pragma unroll
  for (int ii = 0; ii < 4; ii++) {
    int j = threadIdx.x + ii*256;
    if (j < TTOT) {
      float p = vals[ii] * inv;
      unsigned short h, l;
      split1(p, h, l);
      Sh[base + j] = __ushort_as_bfloat16(h);
      Sl[base + j] = __ushort_as_bfloat16(l);
    }
  }
}

__global__ void __launch_bounds__(128) attn_av(
  const bf16* __restrict__ sh_, const bf16* __restrict__ sl_,
  const bf16* __restrict__ vh, const bf16* __restrict__ vl,
  bf16* __restrict__ Oh, bf16* __restrict__ Ol)
{
  __shared__ char sm[32768];
  char* sAh = sm; char* sAl = sm + 8192; char* sBh = sm + 16384; char* sBl = sm + 24576;
  int z = blockIdx.z, b = z >> 3, n = z & 7;
  int d0 = blockIdx.x * 64;
  int tid = threadIdx.x, lane = tid & 31, warp = tid >> 5;
  int wm = (warp >> 1) * 32, wn = (warp & 1) * 32;
  const bf16* Agh = sh_ + (size_t)z*CP*TP;
  const bf16* Agl = sl_ + (size_t)z*CP*TP;
  const bf16* Bgh = vh + (size_t)b*TP*HD + d0;
  const bf16* Bgl = vl + (size_t)b*TP*HD + d0;

  float acc[2][4][4];
  #pragma unroll
  for (int i=0;i<2;i++)
    #pragma unroll
    for (int j=0;j<4;j++)
      #pragma unroll
      for (int e=0;e<4;e++) acc[i][j][e]=0.f;

  int lr = tid >> 3, lc = tid & 7;
  for (int k0 = 0; k0 < TP; k0 += 64) {
    #pragma unroll
    for (int rr = 0; rr < 4; rr++) {
      int r = lr + rr*16;
      int off = swz(r, lc*16);
      *(uint4*)(sAh + off) = *(const uint4*)(Agh + (size_t)r*TP + k0 + lc*8);
      *(uint4*)(sAl + off) = *(const uint4*)(Agl + (size_t)r*TP + k0 + lc*8);
      *(uint4*)(sBh + off) = *(const uint4*)(Bgh + (size_t)(k0 + r)*HD + lc*8);
      *(uint4*)(sBl + off) = *(const uint4*)(Bgl + (size_t)(k0 + r)*HD + lc*8);
    }
    __syncthreads();
    #pragma unroll
    for (int kk = 0; kk < 4; kk++) {
      unsigned Ah[2][4], Al[2][4], Bh[4][2], Bl[4][2];
      #pragma unroll
      for (int mt = 0; mt < 2; mt++) {
        int r = wm + mt*16 + (lane & 15);
        int cb = kk*32 + ((lane >> 4) << 4);
        int off = swz(r, cb);
        ldsm4(Ah[mt][0],Ah[mt][1],Ah[mt][2],Ah[mt][3], su32(sAh + off));
        ldsm4(Al[mt][0],Al[mt][1],Al[mt][2],Al[mt][3], su32(sAl + off));
      }
      #pragma unroll
      for (int p = 0; p < 2; p++) {
        int r = kk*16 + (lane & 15);
        int cb = (wn + p*16)*2 + ((lane >> 4) << 4);
        int off = swz(r, cb);
        unsigned r0,r1,r2,r3;
        ldsm4t(r0,r1,r2,r3, su32(sBh + off));
        Bh[p*2][0]=r0; Bh[p*2][1]=r1; Bh[p*2+1][0]=r2; Bh[p*2+1][1]=r3;
        ldsm4t(r0,r1,r2,r3, su32(sBl + off));
        Bl[p*2][0]=r0; Bl[p*2][1]=r1; Bl[p*2+1][0]=r2; Bl[p*2+1][1]=r3;
      }
      #pragma unroll
      for (int mt = 0; mt < 2; mt++)
        #pragma unroll
        for (int ns = 0; ns < 4; ns++) {
          mma16816(acc[mt][ns], Ah[mt], Bh[ns][0], Bh[ns][1]);
          mma16816(acc[mt][ns], Ah[mt], Bl[ns][0], Bl[ns][1]);
          mma16816(acc[mt][ns], Al[mt], Bh[ns][0], Bh[ns][1]);
        }
    }
    __syncthreads();
  }
  #pragma unroll
  for (int mt = 0; mt < 2; mt++)
    #pragma unroll
    for (int ns = 0; ns < 4; ns++) {
      int c = wm + mt*16 + (lane >> 2);
      int d = d0 + wn + ns*8 + (lane & 3)*2;
      #pragma unroll
      for (int e = 0; e < 4; e++) {
        int cc = c + ((e >= 2) ? 8 : 0);
        int dd = d + (e & 1);
        if (cc < CC) {
          unsigned short h, l;
          split1(acc[mt][ns][e], h, l);
          size_t idx = ((size_t)(b*CC + cc))*(NHH*HD) + n*HD + dd;
          Oh[idx] = __ushort_as_bfloat16(h);
          Ol[idx] = __ushort_as_bfloat16(l);
        }
      }
    }
}

// ---------------- elementwise ----------------
__global__ void qconv_kernel(const float* __restrict__ q, const int* __restrict__ pos,
                             bf16* __restrict__ qh, bf16* __restrict__ ql)
{
  int idx = blockIdx.x * blockDim.x + threadIdx.x;
  if (idx >= MTOT*NHH*128) return;
  int i = idx & 127;
  int mn = idx >> 7;
  int n = mn & 7, m = mn >> 3;
  int b = m / CC, c = m % CC;
  const float* p = q + (size_t)m*(NHH*HD) + n*HD;
  float x1 = p[i], x2 = p[i + 128];
  float ang = (float)pos[c] * expf(-(float)i * (9.210340371976184f/128.f));
  float sn, cs; sincosf(ang, &sn, &cs);
  float o1 = (x1*cs - x2*sn) * 0.0625f;
  float o2 = (x2*cs + x1*sn) * 0.0625f;
  size_t dst = ((size_t)(b*NHH + n)*CP + c)*HD;
  unsigned short h, l;
  split1(o1, h, l); qh[dst+i] = __ushort_as_bfloat16(h); ql[dst+i] = __ushort_as_bfloat16(l);
  split1(o2, h, l); qh[dst+i+128] = __ushort_as_bfloat16(h); ql[dst+i+128] = __ushort_as_bfloat16(l);
}

__global__ void kconv_kernel(const float* __restrict__ pk, const float* __restrict__ knew,
                             const int* __restrict__ pos,
                             bf16* __restrict__ kh, bf16* __restrict__ kl, int layer)
{
  int idx = blockIdx.x * blockDim.x + threadIdx.x;
  if (idx >= BB*TTOT*HD) return;
  int d = idx & 255;
  int bt = idx >> 8;
  int t = bt % TTOT, b = bt / TTOT;
  size_t dst = ((size_t)b*TP + t)*HD;
  unsigned short h, l;
  if (t < PP) {
    float x = pk[(((size_t)layer*BB + b)*PP + t)*HD + d];
    split1(x, h, l);
    kh[dst+d] = __ushort_as_bfloat16(h); kl[dst+d] = __ushort_as_bfloat16(l);
  } else if (d < 128) {
    int c = t - PP;
    const float* p = knew + (size_t)(b*CC + c)*HD;
    float x1 = p[d], x2 = p[d + 128];
    float ang = (float)pos[c] * expf(-(float)d * (9.210340371976184f/128.f));
    float sn, cs; sincosf(ang, &sn, &cs);
    float o1 = x1*cs - x2*sn;
    float o2 = x2*cs + x1*sn;
    split1(o1, h, l); kh[dst+d] = __ushort_as_bfloat16(h); kl[dst+d] = __ushort_as_bfloat16(l);
    split1(o2, h, l); kh[dst+d+128] = __ushort_as_bfloat16(h); kl[dst+d+128] = __ushort_as_bfloat16(l);
  }
}

__global__ void vconv_kernel(const float* __restrict__ pv, const float* __restrict__ vnew,
                             bf16* __restrict__ vh, bf16* __restrict__ vl, int layer)
{
  int idx = blockIdx.x * blockDim.x + threadIdx.x;
  if (idx >= BB*TTOT*HD) return;
  int d = idx & 255;
  int bt = idx >> 8;
  int t = bt % TTOT, b = bt / TTOT;
  float x = (t < PP) ? pv[(((size_t)layer*BB + b)*PP + t)*HD + d]
                     : vnew[(size_t)(b*CC + (t - PP))*HD + d];
  unsigned short h, l;
  split1(x, h, l);
  size_t dst = ((size_t)b*TP + t)*HD;
  vh[dst+d] = __ushort_as_bfloat16(h);
  vl[dst+d] = __ushort_as_bfloat16(l);
}

__global__ void __launch_bounds__(256) rmsnorm_bf(
  const float* __restrict__ x, const float* __restrict__ w,
  bf16* __restrict__ oh, bf16* __restrict__ ol)
{
  int row = blockIdx.x;
  const float* xr = x + (size_t)row*HH;
  float ss = 0.f;
  for (int j = threadIdx.x; j < HH; j += 256) { float v = xr[j]; ss += v*v; }
  ss = blk_reduce(ss, false);
  float sc = rsqrtf(ss * (1.f/HH) + 1e-6f);
  for (int j = threadIdx.x; j < HH; j += 256) {
    float v = xr[j] * sc * w[j];
    unsigned short h, l;
    split1(v, h, l);
    oh[(size_t)row*HH + j] = __ushort_as_bfloat16(h);
    ol[(size_t)row*HH + j] = __ushort_as_bfloat16(l);
  }
}

__global__ void timeemb_bf(const float* __restrict__ ts, bf16* __restrict__ xth, bf16* __restrict__ xtl)
{
  int idx = blockIdx.x * blockDim.x + threadIdx.x;
  if (idx >= MTOT*HH) return;
  int m = idx >> 10, j = idx & 1023;
  int b = m / CC;
  float t = ts[b];
  int i = (j < 512) ? j : (j - 512);
  float period = 4e-3f * expf((float)i * (6.907755278982137f/512.f));
  float ang = 6.283185307179586f * t / period;
  float v = (j < 512) ? sinf(ang) : cosf(ang);
  unsigned short h, l;
  split1(v, h, l);
  size_t dst = (size_t)m*(2*HH) + HH + j;
  xth[dst] = __ushort_as_bfloat16(h);
  xtl[dst] = __ushort_as_bfloat16(l);
}

__global__ void gelumul_bf(const float* __restrict__ gate, const float* __restrict__ up,
                           bf16* __restrict__ mh, bf16* __restrict__ ml)
{
  int idx = blockIdx.x * blockDim.x + threadIdx.x;
  if (idx >= MTOT*MLPD) return;
  float g = gate[idx];
  float t = tanhf(0.7978845608028654f * (g + 0.044715f*g*g*g));
  float v = 0.5f * g * (1.f + t) * up[idx];
  unsigned short h, l;
  split1(v, h, l);
  mh[idx] = __ushort_as_bfloat16(h);
  ml[idx] = __ushort_as_bfloat16(l);
}

// ---------------- orchestration ----------------
extern "C" void kernel_launch(void* const* d_in, const int* in_sizes, int n_in,
                              void* d_out, int out_size)
{
  const float* noisy   = (const float*)d_in[0];
  const float* tstep   = (const float*)d_in[1];
  const int*   pos_ids = (const int*)d_in[2];
  const float* pk      = (const float*)d_in[3];
  const float* pv      = (const float*)d_in[4];
  const float* in_w    = (const float*)d_in[5];
  const float* in_b    = (const float*)d_in[6];
  const float* t_in_w  = (const float*)d_in[7];
  const float* t_in_b  = (const float*)d_in[8];
  const float* t_out_w = (const float*)d_in[9];
  const float* t_out_b = (const float*)d_in[10];
  const float* out_w   = (const float*)d_in[11];
  const float* out_b   = (const float*)d_in[12];
  const float* fn_w    = (const float*)d_in[13];
  const float* ln1_w   = (const float*)d_in[14];
  const float* q_w     = (const float*)d_in[15];
  const float* k_w     = (const float*)d_in[16];
  const float* v_w     = (const float*)d_in[17];
  const float* o_w     = (const float*)d_in[18];
  const float* ln2_w   = (const float*)d_in[19];
  const float* gate_w  = (const float*)d_in[20];
  const float* up_w    = (const float*)d_in[21];
  const float* down_w  = (const float*)d_in[22];
  float* out = (float*)d_out;

  float *x,*q,*k,*v,*s,*gate,*up;
  bf16 *hh,*hl,*xth,*xtl,*midh,*midl,*aoh,*aol,*nh,*nl;
  bf16 *qh,*ql,*kh,*kl,*vh,*vl,*sh,*sl;
  bf16 *qwh,*qwl,*kwh,*kwl,*vwh,*vwl,*owh,*owl,*gwh,*gwl,*uwh,*uwl,*dwh,*dwl;
  bf16 *tinh,*tinl,*touth,*toutl,*outwh,*outwl,*inwh,*inwl;

  cudaGetSymbolAddress((void**)&x, g_x);
  cudaGetSymbolAddress((void**)&q, g_q);
  cudaGetSymbolAddress((void**)&k, g_k);
  cudaGetSymbolAddress((void**)&v, g_v);
  cudaGetSymbolAddress((void**)&s, g_s);
  cudaGetSymbolAddress((void**)&gate, g_gate);
  cudaGetSymbolAddress((void**)&up, g_up);
  cudaGetSymbolAddress((void**)&hh, g_hh);   cudaGetSymbolAddress((void**)&hl, g_hl);
  cudaGetSymbolAddress((void**)&xth, g_xth); cudaGetSymbolAddress((void**)&xtl, g_xtl);
  cudaGetSymbolAddress((void**)&midh, g_midh); cudaGetSymbolAddress((void**)&midl, g_midl);
  cudaGetSymbolAddress((void**)&aoh, g_aoh); cudaGetSymbolAddress((void**)&aol, g_aol);
  cudaGetSymbolAddress((void**)&nh, g_nh);   cudaGetSymbolAddress((void**)&nl, g_nl);
  cudaGetSymbolAddress((void**)&qh, g_qh);   cudaGetSymbolAddress((void**)&ql, g_ql);
  cudaGetSymbolAddress((void**)&kh, g_kh);   cudaGetSymbolAddress((void**)&kl, g_kl);
  cudaGetSymbolAddress((void**)&vh, g_vh);   cudaGetSymbolAddress((void**)&vl, g_vl);
  cudaGetSymbolAddress((void**)&sh, g_sh);   cudaGetSymbolAddress((void**)&sl, g_sl);
  cudaGetSymbolAddress((void**)&qwh, g_qwh); cudaGetSymbolAddress((void**)&qwl, g_qwl);
  cudaGetSymbolAddress((void**)&kwh, g_kwh); cudaGetSymbolAddress((void**)&kwl, g_kwl);
  cudaGetSymbolAddress((void**)&vwh, g_vwh); cudaGetSymbolAddress((void**)&vwl, g_vwl);
  cudaGetSymbolAddress((void**)&owh, g_owh); cudaGetSymbolAddress((void**)&owl, g_owl);
  cudaGetSymbolAddress((void**)&gwh, g_gwh); cudaGetSymbolAddress((void**)&gwl, g_gwl);
  cudaGetSymbolAddress((void**)&uwh, g_uwh); cudaGetSymbolAddress((void**)&uwl, g_uwl);
  cudaGetSymbolAddress((void**)&dwh, g_dwh); cudaGetSymbolAddress((void**)&dwl, g_dwl);
  cudaGetSymbolAddress((void**)&tinh, g_tinh);   cudaGetSymbolAddress((void**)&tinl, g_tinl);
  cudaGetSymbolAddress((void**)&touth, g_touth); cudaGetSymbolAddress((void**)&toutl, g_toutl);
  cudaGetSymbolAddress((void**)&outwh, g_outwh); cudaGetSymbolAddress((void**)&outwl, g_outwl);
  cudaGetSymbolAddress((void**)&inwh, g_inwh);   cudaGetSymbolAddress((void**)&inwl, g_inwl);

  cudaFuncSetAttribute(gemm_bf<9>,  cudaFuncAttributeMaxDynamicSharedMemorySize, SMEM_GEMM);
  cudaFuncSetAttribute(gemm_bf<17>, cudaFuncAttributeMaxDynamicSharedMemorySize, SMEM_GEMM);
  cudaFuncSetAttribute(gemm_bf<18>, cudaFuncAttributeMaxDynamicSharedMemorySize, SMEM_GEMM);
  cudaFuncSetAttribute(qkv_gemm,    cudaFuncAttributeMaxDynamicSharedMemorySize, SMEM_GEMM);
  cudaFuncSetAttribute(gateup_gemm, cudaFuncAttributeMaxDynamicSharedMemorySize, SMEM_GEMM);

  // ---- weight conversion (once per call) ----
  {
    int n;
    n = LNUM*2048*1024/4; convsplit<<<(n+255)/256,256>>>(q_w, qwh, qwl, n);
    n = LNUM*256*1024/4;  convsplit<<<(n+255)/256,256>>>(k_w, kwh, kwl, n);
    n = LNUM*256*1024/4;  convsplit<<<(n+255)/256,256>>>(v_w, vwh, vwl, n);
    n = LNUM*1024*2048/4; convsplit<<<(n+255)/256,256>>>(o_w, owh, owl, n);
    n = LNUM*4096*1024/4; convsplit<<<(n+255)/256,256>>>(gate_w, gwh, gwl, n);
    n = LNUM*4096*1024/4; convsplit<<<(n+255)/256,256>>>(up_w, uwh, uwl, n);
    n = LNUM*1024*4096/4; convsplit<<<(n+255)/256,256>>>(down_w, dwh, dwl, n);
    n = 1024*2048/4;      convsplit<<<(n+255)/256,256>>>(t_in_w, tinh, tinl, n);
    n = 1024*1024/4;      convsplit<<<(n+255)/256,256>>>(t_out_w, touth, toutl, n);
    n = 32*1024/4;        convsplit<<<(n+255)/256,256>>>(out_w, outwh, outwl, n);
    padconv32<<<(1024*32+255)/256,256>>>(in_w, inwh, inwl, 1024);
    padconv32<<<(MTOT*32+255)/256,256>>>(noisy, nh, nl, MTOT);
  }

  // ---- prologue ----
  // action in-proj -> xt[:,0:H] (bf16 hi/lo)
  gemm_bf<9><<<dim3(16,4,1),256,SMEM_GEMM>>>(nh, nl, inwh, inwl, in_b, nullptr, xth, xtl,
                                             MTOT, 1024, 64, 64, 64, 2048);
  timeemb_bf<<<(MTOT*HH+255)/256,256>>>(tstep, xth, xtl);
  // t_in: split-K x2 atomic into fp32 tmp (reuse g_gate front), then silu+split
  cudaMemsetAsync(gate, 0, (size_t)MTOT*1024*sizeof(float));
  gemm_bf<17><<<dim3(16,4,2),256,SMEM_GEMM>>>(xth, xtl, tinh, tinl, t_in_b, gate, nullptr, nullptr,
                                              MTOT, 1024, 1024, 2048, 2048, 1024);
  silu_split<<<(MTOT*1024+255)/256,256>>>(gate, hh, hl, MTOT*1024);
  // t_out: split-K x2 atomic into zeroed x, bias at z==0
  cudaMemsetAsync(x, 0, (size_t)MTOT*HH*sizeof(float));
  gemm_bf<17><<<dim3(16,4,2),256,SMEM_GEMM>>>(hh, hl, touth, toutl, t_out_b, x, nullptr, nullptr,
                                              MTOT, 1024, 512, 1024, 1024, 1024);

  for (int l = 0; l < LNUM; l++) {
    rmsnorm_bf<<<MTOT,256>>>(x, ln1_w + l*HH, hh, hl);
    cudaMemsetAsync(q, 0, (size_t)MTOT*NHH*HD*sizeof(float));
    cudaMemsetAsync(k, 0, (size_t)MTOT*HD*sizeof(float));
    cudaMemsetAsync(v, 0, (size_t)MTOT*HD*sizeof(float));
    qkv_gemm<<<dim3(40,4,2),256,SMEM_GEMM>>>(hh, hl, qwh, qwl, kwh, kwl, vwh, vwl, q, k, v, l);
    qconv_kernel<<<(MTOT*NHH*128+255)/256,256>>>(q, pos_ids, qh, ql);
    kconv_kernel<<<(BB*TTOT*HD+255)/256,256>>>(pk, k, pos_ids, kh, kl, l);
    vconv_kernel<<<(BB*TTOT*HD+255)/256,256>>>(pv, v, vh, vl, l);
    attn_scores<<<dim3(TP/64,1,BB*NHH),128>>>(qh, ql, kh, kl, s);
    softmax_kernel<<<BB*NHH*CC,256>>>(s, sh, sl);
    attn_av<<<dim3(HD/64,1,BB*NHH),128>>>(sh, sl, vh, vl, aoh, aol);
    // O-proj: split-K x4 (K=2048 -> 4x512), atomic residual into x
    gemm_bf<18><<<dim3(16,4,4),256,SMEM_GEMM>>>(aoh, aol,
        owh + (size_t)l*1024*2048, owl + (size_t)l*1024*2048,
        nullptr, x, nullptr, nullptr, MTOT, 1024, 512, 2048, 2048, 1024);
    rmsnorm_bf<<<MTOT,256>>>(x, ln2_w + l*HH, hh, hl);
    gateup_gemm<<<dim3(64,4,2),256,SMEM_GEMM>>>(hh, hl, gwh, gwl, uwh, uwl, gate, up, l);
    gelumul_bf<<<(MTOT*MLPD+255)/256,256>>>(gate, up, midh, midl);
    // down: split-K x4 (K=4096 -> 4x1024), atomic residual into x
    gemm_bf<18><<<dim3(16,4,4),256,SMEM_GEMM>>>(midh, midl,
        dwh + (size_t)l*1024*4096, dwl + (size_t)l*1024*4096,
        nullptr, x, nullptr, nullptr, MTOT, 1024, 1024, 4096, 4096, 1024);
  }

  rmsnorm_bf<<<MTOT,256>>>(x, fn_w, hh, hl);
  // out-proj: split-K x8 (K=1024 -> 8x128), atomic into zeroed out, bias at z==0
  cudaMemsetAsync(out, 0, (size_t)MTOT*AA*sizeof(float));
  gemm_bf<17><<<dim3(1,4,8),256,SMEM_GEMM>>>(hh, hl, outwh, outwl, out_b, out, nullptr, nullptr,
                                             MTOT, 32, 128, 1024, 1024, 32);
}